// round 2
// baseline (speedup 1.0000x reference)
#include <cuda_runtime.h>
#include <math.h>

#define B_ 4
#define S_ 2048
#define D_ 768
#define H_ 12
#define DH_ 64
#define HEADELEMS ((size_t)B_ * H_ * S_ * DH_)   // 6,291,456

// Scratch (no cudaMalloc allowed): q/k/v in [m][b][h][n][e] layout + ctx [b][n][h*DH+e]
__device__ float g_qkv[3 * B_ * H_ * S_ * DH_];
__device__ float g_ctx[B_ * S_ * D_];

// ---------------------------------------------------------------------------
// Kernel 1: fused QKV projection.
// grid = (M/64, 3*H), block = 256. Each CTA computes a 64x64 tile of one
// (matrix m, head h) output. Weight tile for a given (m,h,k0) is a fully
// contiguous 16x64 block of W[h, k0:k0+16, 0:64].
// Scale 1/sqrt(DH)=0.125 is folded into q at write time.
// ---------------------------------------------------------------------------
__global__ void qkv_gemm_kernel(const float* __restrict__ x,
                                const float* __restrict__ Wq, const float* __restrict__ bq,
                                const float* __restrict__ Wk, const float* __restrict__ bk,
                                const float* __restrict__ Wv, const float* __restrict__ bv)
{
    __shared__ float As[16 * 68];   // [k][row] transposed, padded stride 68
    __shared__ float Bs[16 * 64];   // [k][e] natural

    const int tid = threadIdx.x;
    const int tx = tid & 15, ty = tid >> 4;
    const int row0 = blockIdx.x * 64;
    const int m = blockIdx.y / H_;
    const int h = blockIdx.y % H_;

    const float* W    = (m == 0) ? Wq : (m == 1) ? Wk : Wv;
    const float* bias = (m == 0) ? bq : (m == 1) ? bk : bv;
    const float* Wh = W + (size_t)h * D_ * DH_;
    const float* bh = bias + h * DH_;

    const int ar = tid >> 2;        // 0..63 : A row within tile
    const int af = (tid & 3) * 4;   // 0,4,8,12 : k offset within 16-strip

    float acc[4][4] = {};

    for (int k0 = 0; k0 < D_; k0 += 16) {
        // A tile: x[row0+ar][k0+af .. +3], stored transposed
        float4 av = *(const float4*)&x[(size_t)(row0 + ar) * D_ + k0 + af];
        As[(af + 0) * 68 + ar] = av.x;
        As[(af + 1) * 68 + ar] = av.y;
        As[(af + 2) * 68 + ar] = av.z;
        As[(af + 3) * 68 + ar] = av.w;
        // B tile: contiguous 1024 floats
        *(float4*)&Bs[tid * 4] = *(const float4*)&Wh[(size_t)k0 * DH_ + tid * 4];
        __syncthreads();

        #pragma unroll
        for (int kk = 0; kk < 16; kk++) {
            float4 a4 = *(float4*)&As[kk * 68 + ty * 4];
            float4 b4 = *(float4*)&Bs[kk * 64 + tx * 4];
            float aa[4] = {a4.x, a4.y, a4.z, a4.w};
            float bb[4] = {b4.x, b4.y, b4.z, b4.w};
            #pragma unroll
            for (int i = 0; i < 4; i++)
                #pragma unroll
                for (int j = 0; j < 4; j++)
                    acc[i][j] += aa[i] * bb[j];
        }
        __syncthreads();
    }

    const float scale = (m == 0) ? 0.125f : 1.0f;
    float* outbase = g_qkv + (size_t)m * HEADELEMS;
    float4 bv4 = *(const float4*)&bh[tx * 4];
    float bbias[4] = {bv4.x, bv4.y, bv4.z, bv4.w};

    #pragma unroll
    for (int i = 0; i < 4; i++) {
        int row = row0 + ty * 4 + i;
        int b = row >> 11;             // S_ = 2048
        int n = row & (S_ - 1);
        float4 v;
        v.x = (acc[i][0] + bbias[0]) * scale;
        v.y = (acc[i][1] + bbias[1]) * scale;
        v.z = (acc[i][2] + bbias[2]) * scale;
        v.w = (acc[i][3] + bbias[3]) * scale;
        *(float4*)&outbase[(((size_t)b * H_ + h) * S_ + n) * DH_ + tx * 4] = v;
    }
}

// ---------------------------------------------------------------------------
// Kernel 2: flash attention. grid = (S/64, H, B), block = 256, dyn smem.
// Each CTA: 64 q rows, streams kv in 64-row tiles with online softmax.
// Thread (ty,tx) in 16x16 grid owns a 4x4 micro-tile; the 16 threads with
// equal ty share rows -> shfl_xor row reductions (lanes 0-15 / 16-31 groups).
// ---------------------------------------------------------------------------
__global__ void flash_attn_kernel()
{
    extern __shared__ float sm[];
    float* Qt = sm;                  // [64 e][68] transposed q tile
    float* Kt = Qt + 64 * 68;        // [64 e][68] transposed k tile
    float* Vs = Kt + 64 * 68;        // [64 c][64 e] natural v tile
    float* Pt = Vs + 64 * 64;        // [64 c][68] transposed probs tile

    const int tid = threadIdx.x;
    const int tx = tid & 15, ty = tid >> 4;
    const int n0 = blockIdx.x * 64;
    const int h = blockIdx.y, b = blockIdx.z;

    const size_t headoff = (((size_t)b * H_ + h) * S_) * DH_;
    const float* q = g_qkv + headoff;
    const float* k = g_qkv + HEADELEMS + headoff;
    const float* v = g_qkv + 2 * HEADELEMS + headoff;

    // Load Q tile transposed (q already carries the 1/8 scale)
    #pragma unroll
    for (int i = 0; i < 4; i++) {
        int f = tid + i * 256;
        int r = f >> 4, e4 = (f & 15) * 4;
        float4 qv = *(const float4*)&q[(size_t)(n0 + r) * DH_ + e4];
        Qt[(e4 + 0) * 68 + r] = qv.x;
        Qt[(e4 + 1) * 68 + r] = qv.y;
        Qt[(e4 + 2) * 68 + r] = qv.z;
        Qt[(e4 + 3) * 68 + r] = qv.w;
    }

    float o[4][4] = {};
    float mrow[4] = {-INFINITY, -INFINITY, -INFINITY, -INFINITY};
    float lrow[4] = {0.f, 0.f, 0.f, 0.f};

    for (int j0 = 0; j0 < S_; j0 += 64) {
        __syncthreads();   // prior iter readers of Kt/Vs done
        #pragma unroll
        for (int i = 0; i < 4; i++) {
            int f = tid + i * 256;
            int r = f >> 4, e4 = (f & 15) * 4;
            float4 kv = *(const float4*)&k[(size_t)(j0 + r) * DH_ + e4];
            Kt[(e4 + 0) * 68 + r] = kv.x;
            Kt[(e4 + 1) * 68 + r] = kv.y;
            Kt[(e4 + 2) * 68 + r] = kv.z;
            Kt[(e4 + 3) * 68 + r] = kv.w;
            *(float4*)&Vs[r * 64 + e4] = *(const float4*)&v[(size_t)(j0 + r) * DH_ + e4];
        }
        __syncthreads();

        // S = Q K^T (scale already folded into q)
        float s[4][4] = {};
        #pragma unroll
        for (int kk = 0; kk < 64; kk++) {
            float4 a4 = *(float4*)&Qt[kk * 68 + ty * 4];
            float4 b4 = *(float4*)&Kt[kk * 68 + tx * 4];
            float aa[4] = {a4.x, a4.y, a4.z, a4.w};
            float bb[4] = {b4.x, b4.y, b4.z, b4.w};
            #pragma unroll
            for (int i = 0; i < 4; i++)
                #pragma unroll
                for (int j = 0; j < 4; j++)
                    s[i][j] += aa[i] * bb[j];
        }

        // Online softmax per row
        #pragma unroll
        for (int i = 0; i < 4; i++) {
            float rm = fmaxf(fmaxf(s[i][0], s[i][1]), fmaxf(s[i][2], s[i][3]));
            rm = fmaxf(rm, __shfl_xor_sync(0xffffffffu, rm, 1));
            rm = fmaxf(rm, __shfl_xor_sync(0xffffffffu, rm, 2));
            rm = fmaxf(rm, __shfl_xor_sync(0xffffffffu, rm, 4));
            rm = fmaxf(rm, __shfl_xor_sync(0xffffffffu, rm, 8));
            float mnew = fmaxf(mrow[i], rm);
            float corr = __expf(mrow[i] - mnew);   // 0 on first tile (m=-inf)
            float p[4], rs = 0.f;
            #pragma unroll
            for (int j = 0; j < 4; j++) { p[j] = __expf(s[i][j] - mnew); rs += p[j]; }
            rs += __shfl_xor_sync(0xffffffffu, rs, 1);
            rs += __shfl_xor_sync(0xffffffffu, rs, 2);
            rs += __shfl_xor_sync(0xffffffffu, rs, 4);
            rs += __shfl_xor_sync(0xffffffffu, rs, 8);
            lrow[i] = lrow[i] * corr + rs;
            mrow[i] = mnew;
            #pragma unroll
            for (int j = 0; j < 4; j++) o[i][j] *= corr;
            #pragma unroll
            for (int j = 0; j < 4; j++)
                Pt[(tx * 4 + j) * 68 + ty * 4 + i] = p[j];
        }
        __syncthreads();

        // O += P V
        #pragma unroll
        for (int kk = 0; kk < 64; kk++) {
            float4 a4 = *(float4*)&Pt[kk * 68 + ty * 4];
            float4 b4 = *(float4*)&Vs[kk * 64 + tx * 4];
            float aa[4] = {a4.x, a4.y, a4.z, a4.w};
            float bb[4] = {b4.x, b4.y, b4.z, b4.w};
            #pragma unroll
            for (int i = 0; i < 4; i++)
                #pragma unroll
                for (int j = 0; j < 4; j++)
                    o[i][j] += aa[i] * bb[j];
        }
    }

    // Normalize and write ctx in [b][n][h*DH+e] layout (head-concat)
    #pragma unroll
    for (int i = 0; i < 4; i++) {
        float inv = 1.0f / lrow[i];
        int n = n0 + ty * 4 + i;
        float4 w;
        w.x = o[i][0] * inv; w.y = o[i][1] * inv;
        w.z = o[i][2] * inv; w.w = o[i][3] * inv;
        *(float4*)&g_ctx[((size_t)b * S_ + n) * D_ + h * DH_ + tx * 4] = w;
    }
}

// ---------------------------------------------------------------------------
// Kernel 3: output projection ctx[8192,768] @ Wo[768,768] + bo -> out
// grid = (M/64, D/64), block = 256.
// ---------------------------------------------------------------------------
__global__ void out_gemm_kernel(const float* __restrict__ Wo,
                                const float* __restrict__ bo,
                                float* __restrict__ out)
{
    __shared__ float As[16 * 68];
    __shared__ float Bs[16 * 64];

    const int tid = threadIdx.x;
    const int tx = tid & 15, ty = tid >> 4;
    const int row0 = blockIdx.x * 64;
    const int col0 = blockIdx.y * 64;

    const int ar = tid >> 2;
    const int af = (tid & 3) * 4;
    const int bd = tid >> 4;          // 0..15 : B row
    const int be = (tid & 15) * 4;    // 0..60 : B col (float4)

    float acc[4][4] = {};

    for (int k0 = 0; k0 < D_; k0 += 16) {
        float4 av = *(const float4*)&g_ctx[(size_t)(row0 + ar) * D_ + k0 + af];
        As[(af + 0) * 68 + ar] = av.x;
        As[(af + 1) * 68 + ar] = av.y;
        As[(af + 2) * 68 + ar] = av.z;
        As[(af + 3) * 68 + ar] = av.w;
        *(float4*)&Bs[bd * 64 + be] =
            *(const float4*)&Wo[(size_t)(k0 + bd) * D_ + col0 + be];
        __syncthreads();

        #pragma unroll
        for (int kk = 0; kk < 16; kk++) {
            float4 a4 = *(float4*)&As[kk * 68 + ty * 4];
            float4 b4 = *(float4*)&Bs[kk * 64 + tx * 4];
            float aa[4] = {a4.x, a4.y, a4.z, a4.w};
            float bb[4] = {b4.x, b4.y, b4.z, b4.w};
            #pragma unroll
            for (int i = 0; i < 4; i++)
                #pragma unroll
                for (int j = 0; j < 4; j++)
                    acc[i][j] += aa[i] * bb[j];
        }
        __syncthreads();
    }

    float4 bo4 = *(const float4*)&bo[col0 + tx * 4];
    float bbias[4] = {bo4.x, bo4.y, bo4.z, bo4.w};
    #pragma unroll
    for (int i = 0; i < 4; i++) {
        int row = row0 + ty * 4 + i;
        float4 v;
        v.x = acc[i][0] + bbias[0];
        v.y = acc[i][1] + bbias[1];
        v.z = acc[i][2] + bbias[2];
        v.w = acc[i][3] + bbias[3];
        *(float4*)&out[(size_t)row * D_ + col0 + tx * 4] = v;
    }
}

// ---------------------------------------------------------------------------
extern "C" void kernel_launch(void* const* d_in, const int* in_sizes, int n_in,
                              void* d_out, int out_size)
{
    const float* x  = (const float*)d_in[0];
    const float* Wq = (const float*)d_in[1];
    const float* bq = (const float*)d_in[2];
    const float* Wk = (const float*)d_in[3];
    const float* bk = (const float*)d_in[4];
    const float* Wv = (const float*)d_in[5];
    const float* bv = (const float*)d_in[6];
    const float* Wo = (const float*)d_in[7];
    const float* bo = (const float*)d_in[8];
    float* out = (float*)d_out;

    const int flash_smem = (64 * 68 * 3 + 64 * 64) * (int)sizeof(float);  // 68,608 B
    cudaFuncSetAttribute(flash_attn_kernel,
                         cudaFuncAttributeMaxDynamicSharedMemorySize, flash_smem);

    dim3 g1((B_ * S_) / 64, 3 * H_);         // 128 x 36
    qkv_gemm_kernel<<<g1, 256>>>(x, Wq, bq, Wk, bk, Wv, bv);

    dim3 g2(S_ / 64, H_, B_);                // 32 x 12 x 4
    flash_attn_kernel<<<g2, 256, flash_smem>>>();

    dim3 g3((B_ * S_) / 64, D_ / 64);        // 128 x 12
    out_gemm_kernel<<<g3, 256>>>(Wo, bo, out);
}

// round 5
// speedup vs baseline: 3.4641x; 3.4641x over previous
#include <cuda_runtime.h>
#include <cuda_bf16.h>
#include <math.h>
#include <stdint.h>

#define B_ 4
#define S_ 2048
#define D_ 768
#define H_ 12
#define DH_ 64
#define HEADELEMS ((size_t)B_ * H_ * S_ * DH_)   // 6,291,456

// Scratch (no cudaMalloc): q/k/v fp32 in [m][b][h][n][e], ctx fp32 [b][n][h*DH+e]
__device__ float g_qkv[3 * B_ * H_ * S_ * DH_];
__device__ float g_ctx[B_ * S_ * D_];

// ---------------------------------------------------------------------------
// bf16 pack/split helpers. Packed u32: element 'a' in LOW 16 bits, 'b' in HIGH.
// ---------------------------------------------------------------------------
__device__ __forceinline__ uint32_t bfpack(float a, float b) {
    uint32_t r;
    asm("cvt.rn.bf16x2.f32 %0, %1, %2;" : "=r"(r) : "f"(b), "f"(a));
    return r;
}
__device__ __forceinline__ void split2(float a, float b, uint32_t& h, uint32_t& l) {
    h = bfpack(a, b);
    float fa = __bfloat162float(__ushort_as_bfloat16((unsigned short)(h & 0xffffu)));
    float fb = __bfloat162float(__ushort_as_bfloat16((unsigned short)(h >> 16)));
    l = bfpack(a - fa, b - fb);
}
__device__ __forceinline__ void mma16(float d[4], const uint32_t a[4], const uint32_t b[2]) {
    asm volatile(
        "mma.sync.aligned.m16n8k16.row.col.f32.bf16.bf16.f32 "
        "{%0,%1,%2,%3}, {%4,%5,%6,%7}, {%8,%9}, {%0,%1,%2,%3};"
        : "+f"(d[0]), "+f"(d[1]), "+f"(d[2]), "+f"(d[3])
        : "r"(a[0]), "r"(a[1]), "r"(a[2]), "r"(a[3]), "r"(b[0]), "r"(b[1]));
}

// ---------------------------------------------------------------------------
// Kernel 1: fused QKV projection, bf16x3.
// grid = (8192/128, 3*H), block = 256 (8 warps 4x2), CTA tile 128x64, k-chunk 32.
// A: [128 rows][16 kpairs] stride 20 (conflict-free frag reads).
// B: [64 n][16 kpairs] stride 20, transposed on load.
// Output fp32; q scaled by 0.125.
// ---------------------------------------------------------------------------
__global__ __launch_bounds__(256) void qkv_gemm_bf16x3(
    const float* __restrict__ x,
    const float* __restrict__ Wq, const float* __restrict__ bq,
    const float* __restrict__ Wk, const float* __restrict__ bk,
    const float* __restrict__ Wv, const float* __restrict__ bv)
{
    __shared__ uint32_t Ah[128 * 20], Al[128 * 20];
    __shared__ uint32_t Bh[64 * 20],  Bl[64 * 20];

    const int tid = threadIdx.x, lane = tid & 31, w = tid >> 5;
    const int wy = w >> 1, wx = w & 1;
    const int row0 = blockIdx.x * 128;
    const int m = blockIdx.y / H_, h = blockIdx.y % H_;

    const float* W    = (m == 0) ? Wq : (m == 1) ? Wk : Wv;
    const float* bias = (m == 0) ? bq : (m == 1) ? bk : bv;
    const float* Wh = W + (size_t)h * D_ * DH_;
    const float* bh = bias + h * DH_;

    float acc[2][4][4] = {};

    for (int k0 = 0; k0 < D_; k0 += 32) {
        // A tile: 512 units of (row, 8 k) -> 4 packed u32 each
        #pragma unroll
        for (int i = 0; i < 2; i++) {
            int u = tid + i * 256;
            int r = u >> 2, q4 = u & 3;
            const float* src = &x[(size_t)(row0 + r) * D_ + k0 + 8 * q4];
            float4 a0 = *(const float4*)src;
            float4 a1 = *(const float4*)(src + 4);
            uint32_t hh, ll;
            split2(a0.x, a0.y, hh, ll); Ah[r*20 + 4*q4 + 0] = hh; Al[r*20 + 4*q4 + 0] = ll;
            split2(a0.z, a0.w, hh, ll); Ah[r*20 + 4*q4 + 1] = hh; Al[r*20 + 4*q4 + 1] = ll;
            split2(a1.x, a1.y, hh, ll); Ah[r*20 + 4*q4 + 2] = hh; Al[r*20 + 4*q4 + 2] = ll;
            split2(a1.z, a1.w, hh, ll); Ah[r*20 + 4*q4 + 3] = hh; Al[r*20 + 4*q4 + 3] = ll;
        }
        // B tile: (kpair, 4 n) per thread; transpose into [n][kp]
        {
            int kp = tid >> 4, n = (tid & 15) * 4;
            const float* w0 = &Wh[(size_t)(k0 + 2 * kp) * DH_ + n];
            const float* w1 = w0 + DH_;
            float4 b0 = *(const float4*)w0;
            float4 b1 = *(const float4*)w1;
            uint32_t hh, ll;
            split2(b0.x, b1.x, hh, ll); Bh[(n+0)*20 + kp] = hh; Bl[(n+0)*20 + kp] = ll;
            split2(b0.y, b1.y, hh, ll); Bh[(n+1)*20 + kp] = hh; Bl[(n+1)*20 + kp] = ll;
            split2(b0.z, b1.z, hh, ll); Bh[(n+2)*20 + kp] = hh; Bl[(n+2)*20 + kp] = ll;
            split2(b0.w, b1.w, hh, ll); Bh[(n+3)*20 + kp] = hh; Bl[(n+3)*20 + kp] = ll;
        }
        __syncthreads();

        #pragma unroll
        for (int kk = 0; kk < 2; kk++) {
            const int c = kk * 8 + (lane & 3);
            uint32_t ah[2][4], al[2][4], bhf[4][2], blf[4][2];
            #pragma unroll
            for (int mi = 0; mi < 2; mi++) {
                int r = wy * 32 + mi * 16 + (lane >> 2);
                ah[mi][0] = Ah[r*20 + c];       al[mi][0] = Al[r*20 + c];
                ah[mi][1] = Ah[(r+8)*20 + c];   al[mi][1] = Al[(r+8)*20 + c];
                ah[mi][2] = Ah[r*20 + c + 4];   al[mi][2] = Al[r*20 + c + 4];
                ah[mi][3] = Ah[(r+8)*20 + c+4]; al[mi][3] = Al[(r+8)*20 + c+4];
            }
            #pragma unroll
            for (int ni = 0; ni < 4; ni++) {
                int n = wx * 32 + ni * 8 + (lane >> 2);
                bhf[ni][0] = Bh[n*20 + c];     blf[ni][0] = Bl[n*20 + c];
                bhf[ni][1] = Bh[n*20 + c + 4]; blf[ni][1] = Bl[n*20 + c + 4];
            }
            #pragma unroll
            for (int mi = 0; mi < 2; mi++)
                #pragma unroll
                for (int ni = 0; ni < 4; ni++) {
                    mma16(acc[mi][ni], ah[mi], bhf[ni]);
                    mma16(acc[mi][ni], ah[mi], blf[ni]);
                    mma16(acc[mi][ni], al[mi], bhf[ni]);
                }
        }
        __syncthreads();
    }

    const float scale = (m == 0) ? 0.125f : 1.0f;
    float* outp = g_qkv + (size_t)m * HEADELEMS;

    #pragma unroll
    for (int mi = 0; mi < 2; mi++) {
        #pragma unroll
        for (int ni = 0; ni < 4; ni++) {
            int col = wx * 32 + ni * 8 + 2 * (lane & 3);
            float bb0 = bh[col], bb1 = bh[col + 1];
            int rl = row0 + wy * 32 + mi * 16 + (lane >> 2);
            {
                int bb = rl >> 11, n = rl & (S_ - 1);
                float2 v;
                v.x = (acc[mi][ni][0] + bb0) * scale;
                v.y = (acc[mi][ni][1] + bb1) * scale;
                *(float2*)&outp[(((size_t)bb * H_ + h) * S_ + n) * DH_ + col] = v;
            }
            {
                int rh = rl + 8;
                int bb = rh >> 11, n = rh & (S_ - 1);
                float2 v;
                v.x = (acc[mi][ni][2] + bb0) * scale;
                v.y = (acc[mi][ni][3] + bb1) * scale;
                *(float2*)&outp[(((size_t)bb * H_ + h) * S_ + n) * DH_ + col] = v;
            }
        }
    }
}

// ---------------------------------------------------------------------------
// Kernel 2: flash attention, bf16x3. grid = (S/128, H, B), block = 256.
// Each warp owns 16 q rows (softmax warp-local). KV tiles of 64.
// P stays in registers: QK^T C-fragment re-packs directly into PV A-fragment.
// ---------------------------------------------------------------------------
__global__ __launch_bounds__(256) void flash_attn_bf16x3()
{
    extern __shared__ uint32_t sm2[];
    // Phase 1 (Q staging):  Qh = sm2[0..4608), Ql = sm2[4608..9216)   (stride 36)
    // Phase 2 (KV tiles):   Ksh [64][36], Ksl, Vth, Vtl at 0/2304/4608/6912
    uint32_t* Qh  = sm2;
    uint32_t* Ql  = sm2 + 4608;
    uint32_t* Ksh = sm2;
    uint32_t* Ksl = sm2 + 2304;
    uint32_t* Vth = sm2 + 4608;
    uint32_t* Vtl = sm2 + 6912;

    const int tid = threadIdx.x, lane = tid & 31, w = tid >> 5;
    const int n0 = blockIdx.x * 128;
    const int h = blockIdx.y, b = blockIdx.z;

    const size_t headoff = (((size_t)b * H_ + h) * S_) * DH_;
    const float* q = g_qkv + headoff;
    const float* k = g_qkv + HEADELEMS + headoff;
    const float* v = g_qkv + 2 * HEADELEMS + headoff;

    // Stage Q split: [128 rows][32 kpairs] stride 36
    #pragma unroll
    for (int i = 0; i < 4; i++) {
        int u = tid + i * 256;
        int r = u >> 3, q4 = u & 7;
        const float* src = &q[(size_t)(n0 + r) * DH_ + 8 * q4];
        float4 a0 = *(const float4*)src;
        float4 a1 = *(const float4*)(src + 4);
        uint32_t hh, ll;
        split2(a0.x, a0.y, hh, ll); Qh[r*36 + 4*q4 + 0] = hh; Ql[r*36 + 4*q4 + 0] = ll;
        split2(a0.z, a0.w, hh, ll); Qh[r*36 + 4*q4 + 1] = hh; Ql[r*36 + 4*q4 + 1] = ll;
        split2(a1.x, a1.y, hh, ll); Qh[r*36 + 4*q4 + 2] = hh; Ql[r*36 + 4*q4 + 2] = ll;
        split2(a1.z, a1.w, hh, ll); Qh[r*36 + 4*q4 + 3] = hh; Ql[r*36 + 4*q4 + 3] = ll;
    }
    __syncthreads();

    // Per-warp Q fragments (16 rows x 64 k = 4 k16-steps), hi and lo
    uint32_t qh[4][4], ql[4][4];
    {
        int r = w * 16 + (lane >> 2);
        #pragma unroll
        for (int kk = 0; kk < 4; kk++) {
            int c = kk * 8 + (lane & 3);
            qh[kk][0] = Qh[r*36 + c];        ql[kk][0] = Ql[r*36 + c];
            qh[kk][1] = Qh[(r+8)*36 + c];    ql[kk][1] = Ql[(r+8)*36 + c];
            qh[kk][2] = Qh[r*36 + c + 4];    ql[kk][2] = Ql[r*36 + c + 4];
            qh[kk][3] = Qh[(r+8)*36 + c+4];  ql[kk][3] = Ql[(r+8)*36 + c+4];
        }
    }

    float o[8][4] = {};
    float m_lo = -INFINITY, m_hi = -INFINITY;
    float l_lo = 0.f, l_hi = 0.f;

    for (int j0 = 0; j0 < S_; j0 += 64) {
        __syncthreads();   // previous-iter readers done (also covers Q-frag phase)

        // K split: [64 n][32 kpairs over headdim]
        #pragma unroll
        for (int i = 0; i < 2; i++) {
            int u = tid + i * 256;
            int n = u >> 3, q4 = u & 7;
            const float* src = &k[(size_t)(j0 + n) * DH_ + 8 * q4];
            float4 a0 = *(const float4*)src;
            float4 a1 = *(const float4*)(src + 4);
            uint32_t hh, ll;
            split2(a0.x, a0.y, hh, ll); Ksh[n*36 + 4*q4 + 0] = hh; Ksl[n*36 + 4*q4 + 0] = ll;
            split2(a0.z, a0.w, hh, ll); Ksh[n*36 + 4*q4 + 1] = hh; Ksl[n*36 + 4*q4 + 1] = ll;
            split2(a1.x, a1.y, hh, ll); Ksh[n*36 + 4*q4 + 2] = hh; Ksl[n*36 + 4*q4 + 2] = ll;
            split2(a1.z, a1.w, hh, ll); Ksh[n*36 + 4*q4 + 3] = hh; Ksl[n*36 + 4*q4 + 3] = ll;
        }
        // V transposed split: Vt[e][token-pair]
        #pragma unroll
        for (int i = 0; i < 2; i++) {
            int u = tid + i * 256;
            int t = u >> 4, e = (u & 15) * 4;
            const float* v0 = &v[(size_t)(j0 + 2 * t) * DH_ + e];
            const float* v1 = v0 + DH_;
            float4 r0 = *(const float4*)v0;
            float4 r1 = *(const float4*)v1;
            uint32_t hh, ll;
            split2(r0.x, r1.x, hh, ll); Vth[(e+0)*36 + t] = hh; Vtl[(e+0)*36 + t] = ll;
            split2(r0.y, r1.y, hh, ll); Vth[(e+1)*36 + t] = hh; Vtl[(e+1)*36 + t] = ll;
            split2(r0.z, r1.z, hh, ll); Vth[(e+2)*36 + t] = hh; Vtl[(e+2)*36 + t] = ll;
            split2(r0.w, r1.w, hh, ll); Vth[(e+3)*36 + t] = hh; Vtl[(e+3)*36 + t] = ll;
        }
        __syncthreads();

        // S = Q K^T (16 rows x 64 cols per warp)
        float s[8][4] = {};
        #pragma unroll
        for (int kk = 0; kk < 4; kk++) {
            const int c = kk * 8 + (lane & 3);
            #pragma unroll
            for (int ni = 0; ni < 8; ni++) {
                int n = ni * 8 + (lane >> 2);
                uint32_t bh2[2] = { Ksh[n*36 + c], Ksh[n*36 + c + 4] };
                uint32_t bl2[2] = { Ksl[n*36 + c], Ksl[n*36 + c + 4] };
                mma16(s[ni], qh[kk], bh2);
                mma16(s[ni], qh[kk], bl2);
                mma16(s[ni], ql[kk], bh2);
            }
        }

        // Online softmax (rows lane>>2 and (lane>>2)+8; warp-local via quad shfl)
        float mx_lo = -INFINITY, mx_hi = -INFINITY;
        #pragma unroll
        for (int ni = 0; ni < 8; ni++) {
            mx_lo = fmaxf(mx_lo, fmaxf(s[ni][0], s[ni][1]));
            mx_hi = fmaxf(mx_hi, fmaxf(s[ni][2], s[ni][3]));
        }
        mx_lo = fmaxf(mx_lo, __shfl_xor_sync(0xffffffffu, mx_lo, 1));
        mx_lo = fmaxf(mx_lo, __shfl_xor_sync(0xffffffffu, mx_lo, 2));
        mx_hi = fmaxf(mx_hi, __shfl_xor_sync(0xffffffffu, mx_hi, 1));
        mx_hi = fmaxf(mx_hi, __shfl_xor_sync(0xffffffffu, mx_hi, 2));

        float mn_lo = fmaxf(m_lo, mx_lo);
        float mn_hi = fmaxf(m_hi, mx_hi);
        float corr_lo = __expf(m_lo - mn_lo);
        float corr_hi = __expf(m_hi - mn_hi);

        float sum_lo = 0.f, sum_hi = 0.f;
        #pragma unroll
        for (int ni = 0; ni < 8; ni++) {
            s[ni][0] = __expf(s[ni][0] - mn_lo);
            s[ni][1] = __expf(s[ni][1] - mn_lo);
            s[ni][2] = __expf(s[ni][2] - mn_hi);
            s[ni][3] = __expf(s[ni][3] - mn_hi);
            sum_lo += s[ni][0] + s[ni][1];
            sum_hi += s[ni][2] + s[ni][3];
        }
        sum_lo += __shfl_xor_sync(0xffffffffu, sum_lo, 1);
        sum_lo += __shfl_xor_sync(0xffffffffu, sum_lo, 2);
        sum_hi += __shfl_xor_sync(0xffffffffu, sum_hi, 1);
        sum_hi += __shfl_xor_sync(0xffffffffu, sum_hi, 2);

        l_lo = l_lo * corr_lo + sum_lo;  m_lo = mn_lo;
        l_hi = l_hi * corr_hi + sum_hi;  m_hi = mn_hi;

        #pragma unroll
        for (int ni = 0; ni < 8; ni++) {
            o[ni][0] *= corr_lo; o[ni][1] *= corr_lo;
            o[ni][2] *= corr_hi; o[ni][3] *= corr_hi;
        }

        // O += P V : P fragments built in registers from C-fragments of s
        #pragma unroll
        for (int j = 0; j < 4; j++) {
            uint32_t ph[4], pl[4];
            split2(s[2*j][0],   s[2*j][1],   ph[0], pl[0]);
            split2(s[2*j][2],   s[2*j][3],   ph[1], pl[1]);
            split2(s[2*j+1][0], s[2*j+1][1], ph[2], pl[2]);
            split2(s[2*j+1][2], s[2*j+1][3], ph[3], pl[3]);
            const int c = j * 8 + (lane & 3);
            #pragma unroll
            for (int ni = 0; ni < 8; ni++) {
                int e = ni * 8 + (lane >> 2);
                uint32_t bh2[2] = { Vth[e*36 + c], Vth[e*36 + c + 4] };
                uint32_t bl2[2] = { Vtl[e*36 + c], Vtl[e*36 + c + 4] };
                mma16(o[ni], ph, bh2);
                mma16(o[ni], ph, bl2);
                mma16(o[ni], pl, bh2);
            }
        }
    }

    // Normalize and write ctx (fp32)
    float inv_lo = 1.0f / l_lo, inv_hi = 1.0f / l_hi;
    int rl = n0 + w * 16 + (lane >> 2);
    #pragma unroll
    for (int ni = 0; ni < 8; ni++) {
        int col = h * DH_ + ni * 8 + 2 * (lane & 3);
        float2 v0, v1;
        v0.x = o[ni][0] * inv_lo;  v0.y = o[ni][1] * inv_lo;
        v1.x = o[ni][2] * inv_hi;  v1.y = o[ni][3] * inv_hi;
        *(float2*)&g_ctx[((size_t)b * S_ + rl) * D_ + col] = v0;
        *(float2*)&g_ctx[((size_t)b * S_ + rl + 8) * D_ + col] = v1;
    }
}

// ---------------------------------------------------------------------------
// Kernel 3: output projection ctx[8192,768] @ Wo[768,768] + bo, bf16x3.
// grid = (64, 12), block = 256. Same structure as kernel 1.
// ---------------------------------------------------------------------------
__global__ __launch_bounds__(256) void out_gemm_bf16x3(
    const float* __restrict__ Wo, const float* __restrict__ bo,
    float* __restrict__ out)
{
    __shared__ uint32_t Ah[128 * 20], Al[128 * 20];
    __shared__ uint32_t Bh[64 * 20],  Bl[64 * 20];

    const int tid = threadIdx.x, lane = tid & 31, w = tid >> 5;
    const int wy = w >> 1, wx = w & 1;
    const int row0 = blockIdx.x * 128;
    const int col0 = blockIdx.y * 64;

    float acc[2][4][4] = {};

    for (int k0 = 0; k0 < D_; k0 += 32) {
        #pragma unroll
        for (int i = 0; i < 2; i++) {
            int u = tid + i * 256;
            int r = u >> 2, q4 = u & 3;
            const float* src = &g_ctx[(size_t)(row0 + r) * D_ + k0 + 8 * q4];
            float4 a0 = *(const float4*)src;
            float4 a1 = *(const float4*)(src + 4);
            uint32_t hh, ll;
            split2(a0.x, a0.y, hh, ll); Ah[r*20 + 4*q4 + 0] = hh; Al[r*20 + 4*q4 + 0] = ll;
            split2(a0.z, a0.w, hh, ll); Ah[r*20 + 4*q4 + 1] = hh; Al[r*20 + 4*q4 + 1] = ll;
            split2(a1.x, a1.y, hh, ll); Ah[r*20 + 4*q4 + 2] = hh; Al[r*20 + 4*q4 + 2] = ll;
            split2(a1.z, a1.w, hh, ll); Ah[r*20 + 4*q4 + 3] = hh; Al[r*20 + 4*q4 + 3] = ll;
        }
        {
            int kp = tid >> 4, n = (tid & 15) * 4;
            const float* w0 = &Wo[(size_t)(k0 + 2 * kp) * D_ + col0 + n];
            const float* w1 = w0 + D_;
            float4 b0 = *(const float4*)w0;
            float4 b1 = *(const float4*)w1;
            uint32_t hh, ll;
            split2(b0.x, b1.x, hh, ll); Bh[(n+0)*20 + kp] = hh; Bl[(n+0)*20 + kp] = ll;
            split2(b0.y, b1.y, hh, ll); Bh[(n+1)*20 + kp] = hh; Bl[(n+1)*20 + kp] = ll;
            split2(b0.z, b1.z, hh, ll); Bh[(n+2)*20 + kp] = hh; Bl[(n+2)*20 + kp] = ll;
            split2(b0.w, b1.w, hh, ll); Bh[(n+3)*20 + kp] = hh; Bl[(n+3)*20 + kp] = ll;
        }
        __syncthreads();

        #pragma unroll
        for (int kk = 0; kk < 2; kk++) {
            const int c = kk * 8 + (lane & 3);
            uint32_t ah[2][4], al[2][4], bhf[4][2], blf[4][2];
            #pragma unroll
            for (int mi = 0; mi < 2; mi++) {
                int r = wy * 32 + mi * 16 + (lane >> 2);
                ah[mi][0] = Ah[r*20 + c];       al[mi][0] = Al[r*20 + c];
                ah[mi][1] = Ah[(r+8)*20 + c];   al[mi][1] = Al[(r+8)*20 + c];
                ah[mi][2] = Ah[r*20 + c + 4];   al[mi][2] = Al[r*20 + c + 4];
                ah[mi][3] = Ah[(r+8)*20 + c+4]; al[mi][3] = Al[(r+8)*20 + c+4];
            }
            #pragma unroll
            for (int ni = 0; ni < 4; ni++) {
                int n = wx * 32 + ni * 8 + (lane >> 2);
                bhf[ni][0] = Bh[n*20 + c];     blf[ni][0] = Bl[n*20 + c];
                bhf[ni][1] = Bh[n*20 + c + 4]; blf[ni][1] = Bl[n*20 + c + 4];
            }
            #pragma unroll
            for (int mi = 0; mi < 2; mi++)
                #pragma unroll
                for (int ni = 0; ni < 4; ni++) {
                    mma16(acc[mi][ni], ah[mi], bhf[ni]);
                    mma16(acc[mi][ni], ah[mi], blf[ni]);
                    mma16(acc[mi][ni], al[mi], bhf[ni]);
                }
        }
        __syncthreads();
    }

    #pragma unroll
    for (int mi = 0; mi < 2; mi++) {
        #pragma unroll
        for (int ni = 0; ni < 4; ni++) {
            int col = col0 + wx * 32 + ni * 8 + 2 * (lane & 3);
            float bb0 = bo[col], bb1 = bo[col + 1];
            int rl = row0 + wy * 32 + mi * 16 + (lane >> 2);
            float2 v0, v1;
            v0.x = acc[mi][ni][0] + bb0;  v0.y = acc[mi][ni][1] + bb1;
            v1.x = acc[mi][ni][2] + bb0;  v1.y = acc[mi][ni][3] + bb1;
            *(float2*)&out[(size_t)rl * D_ + col] = v0;
            *(float2*)&out[(size_t)(rl + 8) * D_ + col] = v1;
        }
    }
}

// ---------------------------------------------------------------------------
extern "C" void kernel_launch(void* const* d_in, const int* in_sizes, int n_in,
                              void* d_out, int out_size)
{
    const float* x  = (const float*)d_in[0];
    const float* Wq = (const float*)d_in[1];
    const float* bq = (const float*)d_in[2];
    const float* Wk = (const float*)d_in[3];
    const float* bk = (const float*)d_in[4];
    const float* Wv = (const float*)d_in[5];
    const float* bv = (const float*)d_in[6];
    const float* Wo = (const float*)d_in[7];
    const float* bo = (const float*)d_in[8];
    float* out = (float*)d_out;

    const int flash_smem = 9216 * (int)sizeof(uint32_t);   // 36,864 B

    dim3 g1((B_ * S_) / 128, 3 * H_);        // 64 x 36
    qkv_gemm_bf16x3<<<g1, 256>>>(x, Wq, bq, Wk, bk, Wv, bv);

    dim3 g2(S_ / 128, H_, B_);               // 16 x 12 x 4
    flash_attn_bf16x3<<<g2, 256, flash_smem>>>();

    dim3 g3((B_ * S_) / 128, D_ / 64);       // 64 x 12
    out_gemm_bf16x3<<<g3, 256>>>(Wo, bo, out);
}

// round 7
// speedup vs baseline: 3.7338x; 1.0779x over previous
#include <cuda_runtime.h>
#include <cuda_bf16.h>
#include <math.h>
#include <stdint.h>

#define B_ 4
#define S_ 2048
#define D_ 768
#define H_ 12
#define DH_ 64

// Packed-u32 (bf16 pair) array sizes, per hi/lo plane
#define XTOT   ((size_t)8192 * 384)        // x / ctx: [row][384 kpairs]
#define WQKVTOT ((size_t)36 * 64 * 384)    // [m*12+h][n][384]
#define WOTOT  ((size_t)768 * 384)         // [n][384]
#define QTOT   ((size_t)48 * 2048 * 32)    // q/k: [b*12+h][n][32]
#define VTOT   ((size_t)48 * 64 * 1024)    // vt:  [b*12+h][e][1024 token-pairs]

__device__ __align__(16) uint32_t g_xs[2 * XTOT];
__device__ __align__(16) uint32_t g_wqkv[2 * WQKVTOT];
__device__ __align__(16) uint32_t g_wo[2 * WOTOT];
__device__ __align__(16) uint32_t g_q[2 * QTOT];
__device__ __align__(16) uint32_t g_k[2 * QTOT];
__device__ __align__(16) uint32_t g_vt[2 * VTOT];
__device__ __align__(16) uint32_t g_cs[2 * XTOT];

// ---------------------------------------------------------------------------
__device__ __forceinline__ uint32_t bfpack(float a, float b) {
    uint32_t r;
    asm("cvt.rn.bf16x2.f32 %0, %1, %2;" : "=r"(r) : "f"(b), "f"(a));
    return r;
}
__device__ __forceinline__ void split2(float a, float b, uint32_t& h, uint32_t& l) {
    h = bfpack(a, b);
    float fa = __bfloat162float(__ushort_as_bfloat16((unsigned short)(h & 0xffffu)));
    float fb = __bfloat162float(__ushort_as_bfloat16((unsigned short)(h >> 16)));
    l = bfpack(a - fa, b - fb);
}
__device__ __forceinline__ void mma16(float d[4], const uint32_t a[4], const uint32_t b[2]) {
    asm volatile(
        "mma.sync.aligned.m16n8k16.row.col.f32.bf16.bf16.f32 "
        "{%0,%1,%2,%3}, {%4,%5,%6,%7}, {%8,%9}, {%0,%1,%2,%3};"
        : "+f"(d[0]), "+f"(d[1]), "+f"(d[2]), "+f"(d[3])
        : "r"(a[0]), "r"(a[1]), "r"(a[2]), "r"(a[3]), "r"(b[0]), "r"(b[1]));
}

// ---------------------------------------------------------------------------
// Prep kernels: one-time fp32 -> bf16 hi/lo splits
// ---------------------------------------------------------------------------
__global__ void split_x_kernel(const float* __restrict__ x) {
    size_t u = (size_t)blockIdx.x * 256 + threadIdx.x;   // u < XTOT; 2u = row*768+2j
    float2 v = *(const float2*)&x[2 * u];
    uint32_t h, l; split2(v.x, v.y, h, l);
    g_xs[u] = h; g_xs[XTOT + u] = l;
}

__global__ void split_wqkv_kernel(const float* __restrict__ Wq,
                                  const float* __restrict__ Wk,
                                  const float* __restrict__ Wv) {
    size_t u = (size_t)blockIdx.x * 256 + threadIdx.x;   // u < WQKVTOT
    int n = u & 63;
    size_t t = u >> 6;
    int kp = (int)(t % 384);
    int mh = (int)(t / 384);                             // m*12+h
    const float* W = (mh < 12) ? Wq : (mh < 24) ? Wk : Wv;
    const float* base = W + (size_t)(mh % 12) * D_ * DH_;
    float a = base[(size_t)(2 * kp) * 64 + n];
    float b = base[(size_t)(2 * kp + 1) * 64 + n];
    uint32_t h, l; split2(a, b, h, l);
    size_t o = ((size_t)mh * 64 + n) * 384 + kp;
    g_wqkv[o] = h; g_wqkv[WQKVTOT + o] = l;
}

__global__ void split_wo_kernel(const float* __restrict__ Wo) {
    size_t u = (size_t)blockIdx.x * 256 + threadIdx.x;   // u < WOTOT
    int n = (int)(u % 768);
    int kp = (int)(u / 768);
    float a = Wo[(size_t)(2 * kp) * 768 + n];
    float b = Wo[(size_t)(2 * kp + 1) * 768 + n];
    uint32_t h, l; split2(a, b, h, l);
    size_t o = (size_t)n * 384 + kp;
    g_wo[o] = h; g_wo[WOTOT + o] = l;
}

// ---------------------------------------------------------------------------
// Kernel 1: fused QKV projection, bf16x3, pre-split inputs.
// grid = (64, 36), block = 256 (8 warps 4x2), CTA tile 128x64, k-chunk 32 (16 kp).
// q,k written packed hi/lo [n][kp]; v written TRANSPOSED packed [e][token-pair].
// ---------------------------------------------------------------------------
__global__ __launch_bounds__(256) void qkv_gemm(
    const float* __restrict__ bq, const float* __restrict__ bk,
    const float* __restrict__ bv)
{
    __shared__ uint32_t Ah[128 * 20], Al[128 * 20];
    __shared__ uint32_t Bh[64 * 20],  Bl[64 * 20];

    const int tid = threadIdx.x, lane = tid & 31, w = tid >> 5;
    const int wy = w >> 1, wx = w & 1;
    const int row0 = blockIdx.x * 128;
    const int mh = blockIdx.y;                 // m*12+h
    const int m = mh / 12, h = mh % 12;
    const float* bias = (m == 0) ? bq : (m == 1) ? bk : bv;
    const float* bh = bias + h * 64;

    const uint32_t* wbh = g_wqkv + (size_t)mh * 64 * 384;
    const uint32_t* wbl = g_wqkv + WQKVTOT + (size_t)mh * 64 * 384;

    float acc[2][4][4] = {};

    for (int ck = 0; ck < 24; ck++) {
        const int kp0 = ck * 16;
        #pragma unroll
        for (int i = 0; i < 2; i++) {
            int u = tid + i * 256;
            int r = u >> 2, q4 = u & 3;
            size_t src = (size_t)(row0 + r) * 384 + kp0 + 4 * q4;
            *(uint4*)&Ah[r * 20 + 4 * q4] = *(const uint4*)&g_xs[src];
            *(uint4*)&Al[r * 20 + 4 * q4] = *(const uint4*)&g_xs[XTOT + src];
        }
        {
            int r = tid >> 2, q4 = tid & 3;
            size_t src = (size_t)r * 384 + kp0 + 4 * q4;
            *(uint4*)&Bh[r * 20 + 4 * q4] = *(const uint4*)&wbh[src];
            *(uint4*)&Bl[r * 20 + 4 * q4] = *(const uint4*)&wbl[src];
        }
        __syncthreads();

        #pragma unroll
        for (int kk = 0; kk < 2; kk++) {
            const int c = kk * 8 + (lane & 3);
            uint32_t ah[2][4], al[2][4], bhf[4][2], blf[4][2];
            #pragma unroll
            for (int mi = 0; mi < 2; mi++) {
                int r = wy * 32 + mi * 16 + (lane >> 2);
                ah[mi][0] = Ah[r*20 + c];       al[mi][0] = Al[r*20 + c];
                ah[mi][1] = Ah[(r+8)*20 + c];   al[mi][1] = Al[(r+8)*20 + c];
                ah[mi][2] = Ah[r*20 + c + 4];   al[mi][2] = Al[r*20 + c + 4];
                ah[mi][3] = Ah[(r+8)*20 + c+4]; al[mi][3] = Al[(r+8)*20 + c+4];
            }
            #pragma unroll
            for (int ni = 0; ni < 4; ni++) {
                int n = wx * 32 + ni * 8 + (lane >> 2);
                bhf[ni][0] = Bh[n*20 + c];     blf[ni][0] = Bl[n*20 + c];
                bhf[ni][1] = Bh[n*20 + c + 4]; blf[ni][1] = Bl[n*20 + c + 4];
            }
            #pragma unroll
            for (int mi = 0; mi < 2; mi++)
                #pragma unroll
                for (int ni = 0; ni < 4; ni++) {
                    mma16(acc[mi][ni], ah[mi], bhf[ni]);
                    mma16(acc[mi][ni], ah[mi], blf[ni]);
                    mma16(acc[mi][ni], al[mi], bhf[ni]);
                }
        }
        __syncthreads();
    }

    if (m < 2) {
        const float scale = (m == 0) ? 0.125f : 1.0f;
        uint32_t* dh = (m == 0) ? g_q : g_k;
        uint32_t* dl = dh + QTOT;
        #pragma unroll
        for (int mi = 0; mi < 2; mi++) {
            #pragma unroll
            for (int ni = 0; ni < 4; ni++) {
                int col = wx * 32 + ni * 8 + 2 * (lane & 3);
                int cp = col >> 1;
                float b0 = bh[col], b1 = bh[col + 1];
                int rl = row0 + wy * 32 + mi * 16 + (lane >> 2);
                uint32_t hh, ll;
                {
                    int bb = rl >> 11, n = rl & (S_ - 1);
                    size_t o = ((size_t)(bb * 12 + h) * 2048 + n) * 32 + cp;
                    split2((acc[mi][ni][0] + b0) * scale,
                           (acc[mi][ni][1] + b1) * scale, hh, ll);
                    dh[o] = hh; dl[o] = ll;
                }
                {
                    int rh2 = rl + 8;
                    int bb = rh2 >> 11, n = rh2 & (S_ - 1);
                    size_t o = ((size_t)(bb * 12 + h) * 2048 + n) * 32 + cp;
                    split2((acc[mi][ni][2] + b0) * scale,
                           (acc[mi][ni][3] + b1) * scale, hh, ll);
                    dh[o] = hh; dl[o] = ll;
                }
            }
        }
    } else {
        // V: transpose into [e][token-pair] via shfl row-pairing
        const int s1 = (lane >> 2) & 1;
        #pragma unroll
        for (int mi = 0; mi < 2; mi++) {
            #pragma unroll
            for (int ni = 0; ni < 4; ni++) {
                int col = wx * 32 + ni * 8 + 2 * (lane & 3);
                float b0 = bh[col], b1 = bh[col + 1];
                float v0 = acc[mi][ni][0] + b0, v1 = acc[mi][ni][1] + b1;
                float v2 = acc[mi][ni][2] + b0, v3 = acc[mi][ni][3] + b1;
                float p0 = __shfl_xor_sync(0xffffffffu, v0, 4);
                float p1 = __shfl_xor_sync(0xffffffffu, v1, 4);
                float p2 = __shfl_xor_sync(0xffffffffu, v2, 4);
                float p3 = __shfl_xor_sync(0xffffffffu, v3, 4);
                int e = col + s1;
                float fA = s1 ? p1 : v0;     // (even row, e)
                float sA = s1 ? v1 : p0;     // (odd row, e)
                float fB = s1 ? p3 : v2;
                float sB = s1 ? v3 : p2;
                int rl = row0 + wy * 32 + mi * 16 + (lane >> 2);
                int bb = rl >> 11, n = rl & (S_ - 1);
                int np = n >> 1;
                size_t base = ((size_t)(bb * 12 + h) * 64 + e) * 1024;
                uint32_t hh, ll;
                split2(fA, sA, hh, ll);
                g_vt[base + np] = hh;      g_vt[VTOT + base + np] = ll;
                split2(fB, sB, hh, ll);
                g_vt[base + np + 4] = hh;  g_vt[VTOT + base + np + 4] = ll;
            }
        }
    }
}

// ---------------------------------------------------------------------------
// Kernel 2: flash attention, bf16x3, all inputs pre-split.
// grid = (16, 12, 4), block = 256. Each warp owns 16 q rows.
// ---------------------------------------------------------------------------
__global__ __launch_bounds__(256) void flash_attn()
{
    extern __shared__ uint32_t sm2[];
    uint32_t* Qh  = sm2;
    uint32_t* Ql  = sm2 + 4608;
    uint32_t* Ksh = sm2;
    uint32_t* Ksl = sm2 + 2304;
    uint32_t* Vth = sm2 + 4608;
    uint32_t* Vtl = sm2 + 6912;

    const int tid = threadIdx.x, lane = tid & 31, w = tid >> 5;
    const int n0 = blockIdx.x * 128;
    const int h = blockIdx.y, b = blockIdx.z;

    const size_t qb = (size_t)(b * 12 + h) * 2048 * 32;
    const size_t vb = (size_t)(b * 12 + h) * 64 * 1024;

    // Stage Q (raw packed copies)
    #pragma unroll
    for (int i = 0; i < 4; i++) {
        int u = tid + i * 256;
        int r = u >> 3, q4 = u & 7;
        size_t src = qb + (size_t)(n0 + r) * 32 + 4 * q4;
        *(uint4*)&Qh[r * 36 + 4 * q4] = *(const uint4*)&g_q[src];
        *(uint4*)&Ql[r * 36 + 4 * q4] = *(const uint4*)&g_q[QTOT + src];
    }
    __syncthreads();

    uint32_t qh[4][4], ql[4][4];
    {
        int r = w * 16 + (lane >> 2);
        #pragma unroll
        for (int kk = 0; kk < 4; kk++) {
            int c = kk * 8 + (lane & 3);
            qh[kk][0] = Qh[r*36 + c];        ql[kk][0] = Ql[r*36 + c];
            qh[kk][1] = Qh[(r+8)*36 + c];    ql[kk][1] = Ql[(r+8)*36 + c];
            qh[kk][2] = Qh[r*36 + c + 4];    ql[kk][2] = Ql[r*36 + c + 4];
            qh[kk][3] = Qh[(r+8)*36 + c+4];  ql[kk][3] = Ql[(r+8)*36 + c+4];
        }
    }

    float o[8][4] = {};
    float m_lo = -INFINITY, m_hi = -INFINITY;
    float l_lo = 0.f, l_hi = 0.f;

    for (int j0 = 0; j0 < S_; j0 += 64) {
        __syncthreads();
        #pragma unroll
        for (int i = 0; i < 2; i++) {
            int u = tid + i * 256;
            int r = u >> 3, q4 = u & 7;
            size_t ks = qb + (size_t)(j0 + r) * 32 + 4 * q4;
            *(uint4*)&Ksh[r * 36 + 4 * q4] = *(const uint4*)&g_k[ks];
            *(uint4*)&Ksl[r * 36 + 4 * q4] = *(const uint4*)&g_k[QTOT + ks];
            size_t vs = vb + (size_t)r * 1024 + (j0 >> 1) + 4 * q4;   // r = e
            *(uint4*)&Vth[r * 36 + 4 * q4] = *(const uint4*)&g_vt[vs];
            *(uint4*)&Vtl[r * 36 + 4 * q4] = *(const uint4*)&g_vt[VTOT + vs];
        }
        __syncthreads();

        // S = Q K^T
        float s[8][4] = {};
        #pragma unroll
        for (int kk = 0; kk < 4; kk++) {
            const int c = kk * 8 + (lane & 3);
            #pragma unroll
            for (int ni = 0; ni < 8; ni++) {
                int n = ni * 8 + (lane >> 2);
                uint32_t bh2[2] = { Ksh[n*36 + c], Ksh[n*36 + c + 4] };
                uint32_t bl2[2] = { Ksl[n*36 + c], Ksl[n*36 + c + 4] };
                mma16(s[ni], qh[kk], bh2);
                mma16(s[ni], qh[kk], bl2);
                mma16(s[ni], ql[kk], bh2);
            }
        }

        // Online softmax (warp-local)
        float mx_lo = -INFINITY, mx_hi = -INFINITY;
        #pragma unroll
        for (int ni = 0; ni < 8; ni++) {
            mx_lo = fmaxf(mx_lo, fmaxf(s[ni][0], s[ni][1]));
            mx_hi = fmaxf(mx_hi, fmaxf(s[ni][2], s[ni][3]));
        }
        mx_lo = fmaxf(mx_lo, __shfl_xor_sync(0xffffffffu, mx_lo, 1));
        mx_lo = fmaxf(mx_lo, __shfl_xor_sync(0xffffffffu, mx_lo, 2));
        mx_hi = fmaxf(mx_hi, __shfl_xor_sync(0xffffffffu, mx_hi, 1));
        mx_hi = fmaxf(mx_hi, __shfl_xor_sync(0xffffffffu, mx_hi, 2));

        float mn_lo = fmaxf(m_lo, mx_lo);
        float mn_hi = fmaxf(m_hi, mx_hi);
        float corr_lo = __expf(m_lo - mn_lo);
        float corr_hi = __expf(m_hi - mn_hi);

        float sum_lo = 0.f, sum_hi = 0.f;
        #pragma unroll
        for (int ni = 0; ni < 8; ni++) {
            s[ni][0] = __expf(s[ni][0] - mn_lo);
            s[ni][1] = __expf(s[ni][1] - mn_lo);
            s[ni][2] = __expf(s[ni][2] - mn_hi);
            s[ni][3] = __expf(s[ni][3] - mn_hi);
            sum_lo += s[ni][0] + s[ni][1];
            sum_hi += s[ni][2] + s[ni][3];
        }
        sum_lo += __shfl_xor_sync(0xffffffffu, sum_lo, 1);
        sum_lo += __shfl_xor_sync(0xffffffffu, sum_lo, 2);
        sum_hi += __shfl_xor_sync(0xffffffffu, sum_hi, 1);
        sum_hi += __shfl_xor_sync(0xffffffffu, sum_hi, 2);

        l_lo = l_lo * corr_lo + sum_lo;  m_lo = mn_lo;
        l_hi = l_hi * corr_hi + sum_hi;  m_hi = mn_hi;

        #pragma unroll
        for (int ni = 0; ni < 8; ni++) {
            o[ni][0] *= corr_lo; o[ni][1] *= corr_lo;
            o[ni][2] *= corr_hi; o[ni][3] *= corr_hi;
        }

        // O += P V
        #pragma unroll
        for (int j = 0; j < 4; j++) {
            uint32_t ph[4], pl[4];
            split2(s[2*j][0],   s[2*j][1],   ph[0], pl[0]);
            split2(s[2*j][2],   s[2*j][3],   ph[1], pl[1]);
            split2(s[2*j+1][0], s[2*j+1][1], ph[2], pl[2]);
            split2(s[2*j+1][2], s[2*j+1][3], ph[3], pl[3]);
            const int c = j * 8 + (lane & 3);
            #pragma unroll
            for (int ni = 0; ni < 8; ni++) {
                int e = ni * 8 + (lane >> 2);
                uint32_t bh2[2] = { Vth[e*36 + c], Vth[e*36 + c + 4] };
                uint32_t bl2[2] = { Vtl[e*36 + c], Vtl[e*36 + c + 4] };
                mma16(o[ni], ph, bh2);
                mma16(o[ni], ph, bl2);
                mma16(o[ni], pl, bh2);
            }
        }
    }

    // Write ctx pre-split packed [row][384]
    float inv_lo = 1.0f / l_lo, inv_hi = 1.0f / l_hi;
    int rl = n0 + w * 16 + (lane >> 2);
    #pragma unroll
    for (int ni = 0; ni < 8; ni++) {
        int cp = h * 32 + ni * 4 + (lane & 3);
        uint32_t hh, ll;
        split2(o[ni][0] * inv_lo, o[ni][1] * inv_lo, hh, ll);
        size_t o0 = (size_t)(b * 2048 + rl) * 384 + cp;
        g_cs[o0] = hh; g_cs[XTOT + o0] = ll;
        split2(o[ni][2] * inv_hi, o[ni][3] * inv_hi, hh, ll);
        size_t o1 = (size_t)(b * 2048 + rl + 8) * 384 + cp;
        g_cs[o1] = hh; g_cs[XTOT + o1] = ll;
    }
}

// ---------------------------------------------------------------------------
// Kernel 3: output projection, bf16x3, pre-split inputs. fp32 out + bias.
// grid = (64, 12), block = 256.
// ---------------------------------------------------------------------------
__global__ __launch_bounds__(256) void out_gemm(
    const float* __restrict__ bo, float* __restrict__ out)
{
    __shared__ uint32_t Ah[128 * 20], Al[128 * 20];
    __shared__ uint32_t Bh[64 * 20],  Bl[64 * 20];

    const int tid = threadIdx.x, lane = tid & 31, w = tid >> 5;
    const int wy = w >> 1, wx = w & 1;
    const int row0 = blockIdx.x * 128;
    const int col0 = blockIdx.y * 64;

    float acc[2][4][4] = {};

    for (int ck = 0; ck < 24; ck++) {
        const int kp0 = ck * 16;
        #pragma unroll
        for (int i = 0; i < 2; i++) {
            int u = tid + i * 256;
            int r = u >> 2, q4 = u & 3;
            size_t src = (size_t)(row0 + r) * 384 + kp0 + 4 * q4;
            *(uint4*)&Ah[r * 20 + 4 * q4] = *(const uint4*)&g_cs[src];
            *(uint4*)&Al[r * 20 + 4 * q4] = *(const uint4*)&g_cs[XTOT + src];
        }
        {
            int r = tid >> 2, q4 = tid & 3;
            size_t src = (size_t)(col0 + r) * 384 + kp0 + 4 * q4;
            *(uint4*)&Bh[r * 20 + 4 * q4] = *(const uint4*)&g_wo[src];
            *(uint4*)&Bl[r * 20 + 4 * q4] = *(const uint4*)&g_wo[WOTOT + src];
        }
        __syncthreads();

        #pragma unroll
        for (int kk = 0; kk < 2; kk++) {
            const int c = kk * 8 + (lane & 3);
            uint32_t ah[2][4], al[2][4], bhf[4][2], blf[4][2];
            #pragma unroll
            for (int mi = 0; mi < 2; mi++) {
                int r = wy * 32 + mi * 16 + (lane >> 2);
                ah[mi][0] = Ah[r*20 + c];       al[mi][0] = Al[r*20 + c];
                ah[mi][1] = Ah[(r+8)*20 + c];   al[mi][1] = Al[(r+8)*20 + c];
                ah[mi][2] = Ah[r*20 + c + 4];   al[mi][2] = Al[r*20 + c + 4];
                ah[mi][3] = Ah[(r+8)*20 + c+4]; al[mi][3] = Al[(r+8)*20 + c+4];
            }
            #pragma unroll
            for (int ni = 0; ni < 4; ni++) {
                int n = wx * 32 + ni * 8 + (lane >> 2);
                bhf[ni][0] = Bh[n*20 + c];     blf[ni][0] = Bl[n*20 + c];
                bhf[ni][1] = Bh[n*20 + c + 4]; blf[ni][1] = Bl[n*20 + c + 4];
            }
            #pragma unroll
            for (int mi = 0; mi < 2; mi++)
                #pragma unroll
                for (int ni = 0; ni < 4; ni++) {
                    mma16(acc[mi][ni], ah[mi], bhf[ni]);
                    mma16(acc[mi][ni], ah[mi], blf[ni]);
                    mma16(acc[mi][ni], al[mi], bhf[ni]);
                }
        }
        __syncthreads();
    }

    #pragma unroll
    for (int mi = 0; mi < 2; mi++) {
        #pragma unroll
        for (int ni = 0; ni < 4; ni++) {
            int col = col0 + wx * 32 + ni * 8 + 2 * (lane & 3);
            float b0 = bo[col], b1 = bo[col + 1];
            int rl = row0 + wy * 32 + mi * 16 + (lane >> 2);
            float2 v0, v1;
            v0.x = acc[mi][ni][0] + b0;  v0.y = acc[mi][ni][1] + b1;
            v1.x = acc[mi][ni][2] + b0;  v1.y = acc[mi][ni][3] + b1;
            *(float2*)&out[(size_t)rl * D_ + col] = v0;
            *(float2*)&out[(size_t)(rl + 8) * D_ + col] = v1;
        }
    }
}

// ---------------------------------------------------------------------------
extern "C" void kernel_launch(void* const* d_in, const int* in_sizes, int n_in,
                              void* d_out, int out_size)
{
    const float* x  = (const float*)d_in[0];
    const float* Wq = (const float*)d_in[1];
    const float* bq = (const float*)d_in[2];
    const float* Wk = (const float*)d_in[3];
    const float* bk = (const float*)d_in[4];
    const float* Wv = (const float*)d_in[5];
    const float* bv = (const float*)d_in[6];
    const float* Wo = (const float*)d_in[7];
    const float* bo = (const float*)d_in[8];
    float* out = (float*)d_out;

    split_x_kernel<<<(int)(XTOT / 256), 256>>>(x);
    split_wqkv_kernel<<<(int)(WQKVTOT / 256), 256>>>(Wq, Wk, Wv);
    split_wo_kernel<<<(int)(WOTOT / 256), 256>>>(Wo);

    dim3 g1(64, 36);
    qkv_gemm<<<g1, 256>>>(bq, bk, bv);

    const int flash_smem = 9216 * (int)sizeof(uint32_t);   // 36,864 B
    dim3 g2(16, 12, 4);
    flash_attn<<<g2, 256, flash_smem>>>();

    dim3 g3(64, 12);
    out_gemm<<<g3, 256>>>(bo, out);
}

// round 10
// speedup vs baseline: 6.2464x; 1.6730x over previous
#include <cuda_runtime.h>
#include <cuda_fp16.h>
#include <math.h>
#include <stdint.h>

#define B_ 4
#define S_ 2048
#define D_ 768
#define H_ 12
#define DH_ 64

// Packed-u32 (fp16 pair) array sizes
#define XTOT    ((size_t)8192 * 384)      // x / ctx: [row][384 kpairs]
#define WQKVTOT ((size_t)36 * 64 * 384)   // [m*12+h][n][384]  (hi/lo planes)
#define WOTOT   ((size_t)768 * 384)       // [n][384]          (hi/lo planes)
#define QTOT    ((size_t)48 * 2048 * 32)  // q (single) / k (hi/lo): [b*12+h][n][32]
#define VTOT    ((size_t)48 * 64 * 1024)  // vt (hi/lo): [b*12+h][e][1024 token-pairs]

__device__ __align__(16) uint32_t g_xh[XTOT];          // x, plain fp16
__device__ __align__(16) uint32_t g_wqkv[2 * WQKVTOT]; // weights, split
__device__ __align__(16) uint32_t g_wo[2 * WOTOT];     // Wo, split
__device__ __align__(16) uint32_t g_q[QTOT];           // q, plain fp16 (A operand)
__device__ __align__(16) uint32_t g_k[2 * QTOT];       // k, split (B operand)
__device__ __align__(16) uint32_t g_vt[2 * VTOT];      // v transposed, split (B operand)
__device__ __align__(16) uint32_t g_ch[XTOT];          // ctx, plain fp16 (A operand)

// ---------------------------------------------------------------------------
__device__ __forceinline__ uint32_t hpack(float a, float b) {
    __half2 h = __floats2half2_rn(a, b);           // .x = a (low 16), .y = b (high)
    return *reinterpret_cast<uint32_t*>(&h);
}
__device__ __forceinline__ void hsplit2(float a, float b, uint32_t& h, uint32_t& l) {
    __half2 hh = __floats2half2_rn(a, b);
    float2 f = __half22float2(hh);
    h = *reinterpret_cast<uint32_t*>(&hh);
    l = hpack(a - f.x, b - f.y);
}
__device__ __forceinline__ void mmah(float d[4], const uint32_t a[4], const uint32_t b[2]) {
    asm volatile(
        "mma.sync.aligned.m16n8k16.row.col.f32.f16.f16.f32 "
        "{%0,%1,%2,%3}, {%4,%5,%6,%7}, {%8,%9}, {%0,%1,%2,%3};"
        : "+f"(d[0]), "+f"(d[1]), "+f"(d[2]), "+f"(d[3])
        : "r"(a[0]), "r"(a[1]), "r"(a[2]), "r"(a[3]), "r"(b[0]), "r"(b[1]));
}
__device__ __forceinline__ uint32_t s2u(const void* p) {
    return (uint32_t)__cvta_generic_to_shared(p);
}
#define CPA16(dst, src) \
    asm volatile("cp.async.cg.shared.global [%0], [%1], 16;" :: "r"(dst), "l"(src) : "memory")
#define CPC() asm volatile("cp.async.commit_group;" ::: "memory")
#define CPW1() asm volatile("cp.async.wait_group 1;" ::: "memory")
#define CPW0() asm volatile("cp.async.wait_group 0;" ::: "memory")

// ---------------------------------------------------------------------------
// Prep kernels: one-time fp32 -> fp16 (x plain; weights split hi/lo)
// ---------------------------------------------------------------------------
__global__ void split_x_kernel(const float* __restrict__ x) {
    size_t u = (size_t)blockIdx.x * 256 + threadIdx.x;
    float2 v = *(const float2*)&x[2 * u];
    g_xh[u] = hpack(v.x, v.y);
}

__global__ void split_wqkv_kernel(const float* __restrict__ Wq,
                                  const float* __restrict__ Wk,
                                  const float* __restrict__ Wv) {
    size_t u = (size_t)blockIdx.x * 256 + threadIdx.x;
    int n = u & 63;
    size_t t = u >> 6;
    int kp = (int)(t % 384);
    int mh = (int)(t / 384);
    const float* W = (mh < 12) ? Wq : (mh < 24) ? Wk : Wv;
    const float* base = W + (size_t)(mh % 12) * D_ * DH_;
    float a = base[(size_t)(2 * kp) * 64 + n];
    float b = base[(size_t)(2 * kp + 1) * 64 + n];
    uint32_t h, l; hsplit2(a, b, h, l);
    size_t o = ((size_t)mh * 64 + n) * 384 + kp;
    g_wqkv[o] = h; g_wqkv[WQKVTOT + o] = l;
}

__global__ void split_wo_kernel(const float* __restrict__ Wo) {
    size_t u = (size_t)blockIdx.x * 256 + threadIdx.x;
    int n = (int)(u % 768);
    int kp = (int)(u / 768);
    float a = Wo[(size_t)(2 * kp) * 768 + n];
    float b = Wo[(size_t)(2 * kp + 1) * 768 + n];
    uint32_t h, l; hsplit2(a, b, h, l);
    size_t o = (size_t)n * 384 + kp;
    g_wo[o] = h; g_wo[WOTOT + o] = l;
}

// ---------------------------------------------------------------------------
// Kernel 1: fused QKV projection, fp16x2 HMMA, cp.async double-buffered.
// grid = (64, 36), block = 256 (8 warps 4x2), CTA tile 128x64, k-chunk 32.
// ---------------------------------------------------------------------------
__global__ __launch_bounds__(256) void qkv_gemm(
    const float* __restrict__ bq, const float* __restrict__ bk,
    const float* __restrict__ bv)
{
    // A: [2 buf][128 rows x stride 20]; B: [2 buf][2 planes][64 x stride 20]
    __shared__ __align__(16) uint32_t smq[10240];

    const int tid = threadIdx.x, lane = tid & 31, w = tid >> 5;
    const int wy = w >> 1, wx = w & 1;
    const int row0 = blockIdx.x * 128;
    const int mh = blockIdx.y, m = mh / 12, h = mh % 12;
    const float* bias = (m == 0) ? bq : (m == 1) ? bk : bv;
    const float* bh = bias + h * 64;
    const uint32_t* w_h = g_wqkv + (size_t)mh * 64 * 384;
    const uint32_t* w_l = g_wqkv + WQKVTOT + (size_t)mh * 64 * 384;

    auto load_chunk = [&](int ck, int bf) {
        uint32_t* Ab = smq + bf * 2560;
        #pragma unroll
        for (int i = 0; i < 2; i++) {
            int u = tid + i * 256;
            int r = u >> 2, q4 = u & 3;
            CPA16(s2u(&Ab[r * 20 + 4 * q4]),
                  &g_xh[(size_t)(row0 + r) * 384 + ck * 16 + 4 * q4]);
        }
        uint32_t* Bb = smq + 5120 + bf * 2560;
        int r = tid >> 2, q4 = tid & 3;
        CPA16(s2u(&Bb[r * 20 + 4 * q4]), &w_h[(size_t)r * 384 + ck * 16 + 4 * q4]);
        CPA16(s2u(&Bb[1280 + r * 20 + 4 * q4]), &w_l[(size_t)r * 384 + ck * 16 + 4 * q4]);
    };

    float acc[2][4][4] = {};
    load_chunk(0, 0); CPC();

    for (int ck = 0; ck < 24; ck++) {
        const int bf = ck & 1;
        if (ck < 23) { load_chunk(ck + 1, 1 - bf); CPC(); CPW1(); }
        else         { CPW0(); }
        __syncthreads();

        const uint32_t* Ab = smq + bf * 2560;
        const uint32_t* Bh_ = smq + 5120 + bf * 2560;
        const uint32_t* Bl_ = Bh_ + 1280;
        #pragma unroll
        for (int kk = 0; kk < 2; kk++) {
            const int c = kk * 8 + (lane & 3);
            uint32_t a[2][4], bhf[4][2], blf[4][2];
            #pragma unroll
            for (int mi = 0; mi < 2; mi++) {
                int r = wy * 32 + mi * 16 + (lane >> 2);
                a[mi][0] = Ab[r * 20 + c];
                a[mi][1] = Ab[(r + 8) * 20 + c];
                a[mi][2] = Ab[r * 20 + c + 4];
                a[mi][3] = Ab[(r + 8) * 20 + c + 4];
            }
            #pragma unroll
            for (int ni = 0; ni < 4; ni++) {
                int n = wx * 32 + ni * 8 + (lane >> 2);
                bhf[ni][0] = Bh_[n * 20 + c];     blf[ni][0] = Bl_[n * 20 + c];
                bhf[ni][1] = Bh_[n * 20 + c + 4]; blf[ni][1] = Bl_[n * 20 + c + 4];
            }
            #pragma unroll
            for (int mi = 0; mi < 2; mi++)
                #pragma unroll
                for (int ni = 0; ni < 4; ni++) {
                    mmah(acc[mi][ni], a[mi], bhf[ni]);
                    mmah(acc[mi][ni], a[mi], blf[ni]);
                }
        }
        __syncthreads();
    }

    if (m == 0) {
        // q: plain fp16, scale folded
        #pragma unroll
        for (int mi = 0; mi < 2; mi++) {
            #pragma unroll
            for (int ni = 0; ni < 4; ni++) {
                int col = wx * 32 + ni * 8 + 2 * (lane & 3);
                int cp = col >> 1;
                float b0 = bh[col], b1 = bh[col + 1];
                int rl = row0 + wy * 32 + mi * 16 + (lane >> 2);
                {
                    int bb = rl >> 11, n = rl & (S_ - 1);
                    g_q[((size_t)(bb * 12 + h) * 2048 + n) * 32 + cp] =
                        hpack((acc[mi][ni][0] + b0) * 0.125f,
                              (acc[mi][ni][1] + b1) * 0.125f);
                }
                {
                    int rh2 = rl + 8;
                    int bb = rh2 >> 11, n = rh2 & (S_ - 1);
                    g_q[((size_t)(bb * 12 + h) * 2048 + n) * 32 + cp] =
                        hpack((acc[mi][ni][2] + b0) * 0.125f,
                              (acc[mi][ni][3] + b1) * 0.125f);
                }
            }
        }
    } else if (m == 1) {
        // k: split hi/lo
        #pragma unroll
        for (int mi = 0; mi < 2; mi++) {
            #pragma unroll
            for (int ni = 0; ni < 4; ni++) {
                int col = wx * 32 + ni * 8 + 2 * (lane & 3);
                int cp = col >> 1;
                float b0 = bh[col], b1 = bh[col + 1];
                int rl = row0 + wy * 32 + mi * 16 + (lane >> 2);
                uint32_t hh, ll;
                {
                    int bb = rl >> 11, n = rl & (S_ - 1);
                    size_t o = ((size_t)(bb * 12 + h) * 2048 + n) * 32 + cp;
                    hsplit2(acc[mi][ni][0] + b0, acc[mi][ni][1] + b1, hh, ll);
                    g_k[o] = hh; g_k[QTOT + o] = ll;
                }
                {
                    int rh2 = rl + 8;
                    int bb = rh2 >> 11, n = rh2 & (S_ - 1);
                    size_t o = ((size_t)(bb * 12 + h) * 2048 + n) * 32 + cp;
                    hsplit2(acc[mi][ni][2] + b0, acc[mi][ni][3] + b1, hh, ll);
                    g_k[o] = hh; g_k[QTOT + o] = ll;
                }
            }
        }
    } else {
        // v: transpose into [e][token-pair] via shfl row-pairing, split hi/lo
        const int s1 = (lane >> 2) & 1;
        #pragma unroll
        for (int mi = 0; mi < 2; mi++) {
            #pragma unroll
            for (int ni = 0; ni < 4; ni++) {
                int col = wx * 32 + ni * 8 + 2 * (lane & 3);
                float b0 = bh[col], b1 = bh[col + 1];
                float v0 = acc[mi][ni][0] + b0, v1 = acc[mi][ni][1] + b1;
                float v2 = acc[mi][ni][2] + b0, v3 = acc[mi][ni][3] + b1;
                float p0 = __shfl_xor_sync(0xffffffffu, v0, 4);
                float p1 = __shfl_xor_sync(0xffffffffu, v1, 4);
                float p2 = __shfl_xor_sync(0xffffffffu, v2, 4);
                float p3 = __shfl_xor_sync(0xffffffffu, v3, 4);
                int e = col + s1;
                float fA = s1 ? p1 : v0;
                float sA = s1 ? v1 : p0;
                float fB = s1 ? p3 : v2;
                float sB = s1 ? v3 : p2;
                int rl = row0 + wy * 32 + mi * 16 + (lane >> 2);
                int bb = rl >> 11, n = rl & (S_ - 1);
                int np = n >> 1;
                size_t base = ((size_t)(bb * 12 + h) * 64 + e) * 1024;
                uint32_t hh, ll;
                hsplit2(fA, sA, hh, ll);
                g_vt[base + np] = hh;      g_vt[VTOT + base + np] = ll;
                hsplit2(fB, sB, hh, ll);
                g_vt[base + np + 4] = hh;  g_vt[VTOT + base + np + 4] = ll;
            }
        }
    }
}

// ---------------------------------------------------------------------------
// Kernel 2: flash attention, fp16x2, cp.async double-buffered KV tiles.
// grid = (16, 12, 4), block = 256. Each warp owns 16 q rows (warp-local softmax).
// ---------------------------------------------------------------------------
__global__ __launch_bounds__(256) void flash_attn()
{
    extern __shared__ __align__(16) uint32_t sm2[];
    // buf bf: Kh @ bf*9216, Kl @ +2304, Vh @ +4608, Vl @ +6912 (stride 36)
    const int tid = threadIdx.x, lane = tid & 31, w = tid >> 5;
    const int n0 = blockIdx.x * 128;
    const int h = blockIdx.y, b = blockIdx.z;
    const size_t qb = (size_t)(b * 12 + h) * 2048 * 32;
    const size_t vb = (size_t)(b * 12 + h) * 64 * 1024;

    // Stage Q (plain fp16) into sm2[0..4608)
    #pragma unroll
    for (int i = 0; i < 4; i++) {
        int u = tid + i * 256;
        int r = u >> 3, q4 = u & 7;
        *(uint4*)&sm2[r * 36 + 4 * q4] =
            *(const uint4*)&g_q[qb + (size_t)(n0 + r) * 32 + 4 * q4];
    }
    __syncthreads();

    uint32_t qa[4][4];
    {
        int r = w * 16 + (lane >> 2);
        #pragma unroll
        for (int kk = 0; kk < 4; kk++) {
            int c = kk * 8 + (lane & 3);
            qa[kk][0] = sm2[r * 36 + c];
            qa[kk][1] = sm2[(r + 8) * 36 + c];
            qa[kk][2] = sm2[r * 36 + c + 4];
            qa[kk][3] = sm2[(r + 8) * 36 + c + 4];
        }
    }
    __syncthreads();   // Q stage area now reusable as buf0

    auto load_tile = [&](int t, int bf) {
        uint32_t* base = sm2 + bf * 9216;
        #pragma unroll
        for (int i = 0; i < 2; i++) {
            int u = tid + i * 256;
            int r = u >> 3, q4 = u & 7;
            size_t ks = qb + (size_t)(t * 64 + r) * 32 + 4 * q4;
            CPA16(s2u(&base[r * 36 + 4 * q4]),        &g_k[ks]);
            CPA16(s2u(&base[2304 + r * 36 + 4 * q4]), &g_k[QTOT + ks]);
            size_t vs = vb + (size_t)r * 1024 + t * 32 + 4 * q4;
            CPA16(s2u(&base[4608 + r * 36 + 4 * q4]), &g_vt[vs]);
            CPA16(s2u(&base[6912 + r * 36 + 4 * q4]), &g_vt[VTOT + vs]);
        }
    };

    float o[8][4] = {};
    float m_lo = -INFINITY, m_hi = -INFINITY;
    float l_lo = 0.f, l_hi = 0.f;

    load_tile(0, 0); CPC();

    for (int t = 0; t < 32; t++) {
        const int bf = t & 1;
        if (t < 31) { load_tile(t + 1, 1 - bf); CPC(); CPW1(); }
        else        { CPW0(); }
        __syncthreads();

        const uint32_t* Kh = sm2 + bf * 9216;
        const uint32_t* Kl = Kh + 2304;
        const uint32_t* Vh = Kh + 4608;
        const uint32_t* Vl = Kh + 6912;

        // S = Q K^T
        float s[8][4] = {};
        #pragma unroll
        for (int kk = 0; kk < 4; kk++) {
            const int c = kk * 8 + (lane & 3);
            #pragma unroll
            for (int ni = 0; ni < 8; ni++) {
                int n = ni * 8 + (lane >> 2);
                uint32_t kh2[2] = { Kh[n * 36 + c], Kh[n * 36 + c + 4] };
                uint32_t kl2[2] = { Kl[n * 36 + c], Kl[n * 36 + c + 4] };
                mmah(s[ni], qa[kk], kh2);
                mmah(s[ni], qa[kk], kl2);
            }
        }

        // Online softmax (warp-local, quad shfl)
        float mx_lo = -INFINITY, mx_hi = -INFINITY;
        #pragma unroll
        for (int ni = 0; ni < 8; ni++) {
            mx_lo = fmaxf(mx_lo, fmaxf(s[ni][0], s[ni][1]));
            mx_hi = fmaxf(mx_hi, fmaxf(s[ni][2], s[ni][3]));
        }
        mx_lo = fmaxf(mx_lo, __shfl_xor_sync(0xffffffffu, mx_lo, 1));
        mx_lo = fmaxf(mx_lo, __shfl_xor_sync(0xffffffffu, mx_lo, 2));
        mx_hi = fmaxf(mx_hi, __shfl_xor_sync(0xffffffffu, mx_hi, 1));
        mx_hi = fmaxf(mx_hi, __shfl_xor_sync(0xffffffffu, mx_hi, 2));

        float mn_lo = fmaxf(m_lo, mx_lo);
        float mn_hi = fmaxf(m_hi, mx_hi);
        float corr_lo = __expf(m_lo - mn_lo);
        float corr_hi = __expf(m_hi - mn_hi);

        float sum_lo = 0.f, sum_hi = 0.f;
        #pragma unroll
        for (int ni = 0; ni < 8; ni++) {
            s[ni][0] = __expf(s[ni][0] - mn_lo);
            s[ni][1] = __expf(s[ni][1] - mn_lo);
            s[ni][2] = __expf(s[ni][2] - mn_hi);
            s[ni][3] = __expf(s[ni][3] - mn_hi);
            sum_lo += s[ni][0] + s[ni][1];
            sum_hi += s[ni][2] + s[ni][3];
        }
        sum_lo += __shfl_xor_sync(0xffffffffu, sum_lo, 1);
        sum_lo += __shfl_xor_sync(0xffffffffu, sum_lo, 2);
        sum_hi += __shfl_xor_sync(0xffffffffu, sum_hi, 1);
        sum_hi += __shfl_xor_sync(0xffffffffu, sum_hi, 2);

        l_lo = l_lo * corr_lo + sum_lo;  m_lo = mn_lo;
        l_hi = l_hi * corr_hi + sum_hi;  m_hi = mn_hi;

        #pragma unroll
        for (int ni = 0; ni < 8; ni++) {
            o[ni][0] *= corr_lo; o[ni][1] *= corr_lo;
            o[ni][2] *= corr_hi; o[ni][3] *= corr_hi;
        }

        // O += P V  (P packed plain fp16 from registers)
        #pragma unroll
        for (int j = 0; j < 4; j++) {
            uint32_t ph[4];
            ph[0] = hpack(s[2*j][0],   s[2*j][1]);
            ph[1] = hpack(s[2*j][2],   s[2*j][3]);
            ph[2] = hpack(s[2*j+1][0], s[2*j+1][1]);
            ph[3] = hpack(s[2*j+1][2], s[2*j+1][3]);
            const int c = j * 8 + (lane & 3);
            #pragma unroll
            for (int ni = 0; ni < 8; ni++) {
                int e = ni * 8 + (lane >> 2);
                uint32_t vh2[2] = { Vh[e * 36 + c], Vh[e * 36 + c + 4] };
                uint32_t vl2[2] = { Vl[e * 36 + c], Vl[e * 36 + c + 4] };
                mmah(o[ni], ph, vh2);
                mmah(o[ni], ph, vl2);
            }
        }
        __syncthreads();
    }

    // ctx: plain fp16 packed [row][384]
    float inv_lo = 1.0f / l_lo, inv_hi = 1.0f / l_hi;
    int rl = n0 + w * 16 + (lane >> 2);
    #pragma unroll
    for (int ni = 0; ni < 8; ni++) {
        int cp = h * 32 + ni * 4 + (lane & 3);
        g_ch[(size_t)(b * 2048 + rl) * 384 + cp] =
            hpack(o[ni][0] * inv_lo, o[ni][1] * inv_lo);
        g_ch[(size_t)(b * 2048 + rl + 8) * 384 + cp] =
            hpack(o[ni][2] * inv_hi, o[ni][3] * inv_hi);
    }
}

// ---------------------------------------------------------------------------
// Kernel 3: output projection, fp16x2, cp.async double-buffered.
// grid = (64, 12), block = 256. fp32 out + bias.
// ---------------------------------------------------------------------------
__global__ __launch_bounds__(256) void out_gemm(
    const float* __restrict__ bo, float* __restrict__ out)
{
    __shared__ __align__(16) uint32_t smq[10240];

    const int tid = threadIdx.x, lane = tid & 31, w = tid >> 5;
    const int wy = w >> 1, wx = w & 1;
    const int row0 = blockIdx.x * 128;
    const int col0 = blockIdx.y * 64;
    const uint32_t* w_h = g_wo + (size_t)col0 * 384;
    const uint32_t* w_l = g_wo + WOTOT + (size_t)col0 * 384;

    auto load_chunk = [&](int ck, int bf) {
        uint32_t* Ab = smq + bf * 2560;
        #pragma unroll
        for (int i = 0; i < 2; i++) {
            int u = tid + i * 256;
            int r = u >> 2, q4 = u & 3;
            CPA16(s2u(&Ab[r * 20 + 4 * q4]),
                  &g_ch[(size_t)(row0 + r) * 384 + ck * 16 + 4 * q4]);
        }
        uint32_t* Bb = smq + 5120 + bf * 2560;
        int r = tid >> 2, q4 = tid & 3;
        CPA16(s2u(&Bb[r * 20 + 4 * q4]), &w_h[(size_t)r * 384 + ck * 16 + 4 * q4]);
        CPA16(s2u(&Bb[1280 + r * 20 + 4 * q4]), &w_l[(size_t)r * 384 + ck * 16 + 4 * q4]);
    };

    float acc[2][4][4] = {};
    load_chunk(0, 0); CPC();

    for (int ck = 0; ck < 24; ck++) {
        const int bf = ck & 1;
        if (ck < 23) { load_chunk(ck + 1, 1 - bf); CPC(); CPW1(); }
        else         { CPW0(); }
        __syncthreads();

        const uint32_t* Ab = smq + bf * 2560;
        const uint32_t* Bh_ = smq + 5120 + bf * 2560;
        const uint32_t* Bl_ = Bh_ + 1280;
        #pragma unroll
        for (int kk = 0; kk < 2; kk++) {
            const int c = kk * 8 + (lane & 3);
            uint32_t a[2][4], bhf[4][2], blf[4][2];
            #pragma unroll
            for (int mi = 0; mi < 2; mi++) {
                int r = wy * 32 + mi * 16 + (lane >> 2);
                a[mi][0] = Ab[r * 20 + c];
                a[mi][1] = Ab[(r + 8) * 20 + c];
                a[mi][2] = Ab[r * 20 + c + 4];
                a[mi][3] = Ab[(r + 8) * 20 + c + 4];
            }
            #pragma unroll
            for (int ni = 0; ni < 4; ni++) {
                int n = wx * 32 + ni * 8 + (lane >> 2);
                bhf[ni][0] = Bh_[n * 20 + c];     blf[ni][0] = Bl_[n * 20 + c];
                bhf[ni][1] = Bh_[n * 20 + c + 4]; blf[ni][1] = Bl_[n * 20 + c + 4];
            }
            #pragma unroll
            for (int mi = 0; mi < 2; mi++)
                #pragma unroll
                for (int ni = 0; ni < 4; ni++) {
                    mmah(acc[mi][ni], a[mi], bhf[ni]);
                    mmah(acc[mi][ni], a[mi], blf[ni]);
                }
        }
        __syncthreads();
    }

    #pragma unroll
    for (int mi = 0; mi < 2; mi++) {
        #pragma unroll
        for (int ni = 0; ni < 4; ni++) {
            int col = col0 + wx * 32 + ni * 8 + 2 * (lane & 3);
            float b0 = bo[col], b1 = bo[col + 1];
            int rl = row0 + wy * 32 + mi * 16 + (lane >> 2);
            float2 v0, v1;
            v0.x = acc[mi][ni][0] + b0;  v0.y = acc[mi][ni][1] + b1;
            v1.x = acc[mi][ni][2] + b0;  v1.y = acc[mi][ni][3] + b1;
            *(float2*)&out[(size_t)rl * D_ + col] = v0;
            *(float2*)&out[(size_t)(rl + 8) * D_ + col] = v1;
        }
    }
}

// ---------------------------------------------------------------------------
extern "C" void kernel_launch(void* const* d_in, const int* in_sizes, int n_in,
                              void* d_out, int out_size)
{
    const float* x  = (const float*)d_in[0];
    const float* Wq = (const float*)d_in[1];
    const float* bq = (const float*)d_in[2];
    const float* Wk = (const float*)d_in[3];
    const float* bk = (const float*)d_in[4];
    const float* Wv = (const float*)d_in[5];
    const float* bv = (const float*)d_in[6];
    const float* Wo = (const float*)d_in[7];
    const float* bo = (const float*)d_in[8];
    float* out = (float*)d_out;

    const int flash_smem = 18432 * (int)sizeof(uint32_t);   // 73,728 B
    cudaFuncSetAttribute(flash_attn,
                         cudaFuncAttributeMaxDynamicSharedMemorySize, flash_smem);

    split_x_kernel<<<(int)(XTOT / 256), 256>>>(x);
    split_wqkv_kernel<<<(int)(WQKVTOT / 256), 256>>>(Wq, Wk, Wv);
    split_wo_kernel<<<(int)(WOTOT / 256), 256>>>(Wo);

    dim3 g1(64, 36);
    qkv_gemm<<<g1, 256>>>(bq, bk, bv);

    dim3 g2(16, 12, 4);
    flash_attn<<<g2, 256, flash_smem>>>();

    dim3 g3(64, 12);
    out_gemm<<<g3, 256>>>(bo, out);
}

// round 14
// speedup vs baseline: 6.9143x; 1.1069x over previous
#include <cuda_runtime.h>
#include <cuda_fp16.h>
#include <math.h>
#include <stdint.h>

#define B_ 4
#define S_ 2048
#define D_ 768
#define H_ 12
#define DH_ 64

// Packed-u32 (fp16 pair) array sizes
#define XTOT    ((size_t)8192 * 384)      // x / ctx: [row][384 kpairs]
#define WQKVTOT ((size_t)36 * 64 * 384)   // [m*12+h][n][384]  (hi/lo planes)
#define WOTOT   ((size_t)768 * 384)       // [n][384]          (hi/lo planes)
#define QTOT    ((size_t)48 * 2048 * 32)  // q (single) / k (hi/lo): [b*12+h][n][32]
#define VTOT    ((size_t)48 * 64 * 1024)  // vt (hi/lo): [b*12+h][e][1024 token-pairs]

__device__ __align__(16) uint32_t g_xh[XTOT];
__device__ __align__(16) uint32_t g_wqkv[2 * WQKVTOT];
__device__ __align__(16) uint32_t g_wo[2 * WOTOT];
__device__ __align__(16) uint32_t g_q[QTOT];
__device__ __align__(16) uint32_t g_k[2 * QTOT];
__device__ __align__(16) uint32_t g_vt[2 * VTOT];
__device__ __align__(16) uint32_t g_ch[XTOT];

// ---------------------------------------------------------------------------
__device__ __forceinline__ uint32_t hpack(float a, float b) {
    __half2 h = __floats2half2_rn(a, b);
    return *reinterpret_cast<uint32_t*>(&h);
}
__device__ __forceinline__ void hsplit2(float a, float b, uint32_t& h, uint32_t& l) {
    __half2 hh = __floats2half2_rn(a, b);
    float2 f = __half22float2(hh);
    h = *reinterpret_cast<uint32_t*>(&hh);
    l = hpack(a - f.x, b - f.y);
}
__device__ __forceinline__ void mmah(float d[4], const uint32_t a[4], const uint32_t b[2]) {
    asm volatile(
        "mma.sync.aligned.m16n8k16.row.col.f32.f16.f16.f32 "
        "{%0,%1,%2,%3}, {%4,%5,%6,%7}, {%8,%9}, {%0,%1,%2,%3};"
        : "+f"(d[0]), "+f"(d[1]), "+f"(d[2]), "+f"(d[3])
        : "r"(a[0]), "r"(a[1]), "r"(a[2]), "r"(a[3]), "r"(b[0]), "r"(b[1]));
}
__device__ __forceinline__ uint32_t s2u(const void* p) {
    return (uint32_t)__cvta_generic_to_shared(p);
}
#define LDSM4(R0, R1, R2, R3, ADDR) \
    asm volatile("ldmatrix.sync.aligned.m8n8.x4.shared.b16 {%0,%1,%2,%3}, [%4];" \
                 : "=r"(R0), "=r"(R1), "=r"(R2), "=r"(R3) : "r"(ADDR))
#define CPA16(dst, src) \
    asm volatile("cp.async.cg.shared.global [%0], [%1], 16;" :: "r"(dst), "l"(src) : "memory")
#define CPC() asm volatile("cp.async.commit_group;" ::: "memory")
#define CPW1() asm volatile("cp.async.wait_group 1;" ::: "memory")
#define CPW0() asm volatile("cp.async.wait_group 0;" ::: "memory")

// ---------------------------------------------------------------------------
// Prep kernels
// ---------------------------------------------------------------------------
__global__ void split_x_kernel(const float* __restrict__ x) {
    size_t u = (size_t)blockIdx.x * 256 + threadIdx.x;
    float2 v = *(const float2*)&x[2 * u];
    g_xh[u] = hpack(v.x, v.y);
}

__global__ void split_wqkv_kernel(const float* __restrict__ Wq,
                                  const float* __restrict__ Wk,
                                  const float* __restrict__ Wv) {
    size_t u = (size_t)blockIdx.x * 256 + threadIdx.x;
    int n = u & 63;
    size_t t = u >> 6;
    int kp = (int)(t % 384);
    int mh = (int)(t / 384);
    const float* W = (mh < 12) ? Wq : (mh < 24) ? Wk : Wv;
    const float* base = W + (size_t)(mh % 12) * D_ * DH_;
    float a = base[(size_t)(2 * kp) * 64 + n];
    float b = base[(size_t)(2 * kp + 1) * 64 + n];
    uint32_t h, l; hsplit2(a, b, h, l);
    size_t o = ((size_t)mh * 64 + n) * 384 + kp;
    g_wqkv[o] = h; g_wqkv[WQKVTOT + o] = l;
}

__global__ void split_wo_kernel(const float* __restrict__ Wo) {
    size_t u = (size_t)blockIdx.x * 256 + threadIdx.x;
    int n = (int)(u % 768);
    int kp = (int)(u / 768);
    float a = Wo[(size_t)(2 * kp) * 768 + n];
    float b = Wo[(size_t)(2 * kp + 1) * 768 + n];
    uint32_t h, l; hsplit2(a, b, h, l);
    size_t o = (size_t)n * 384 + kp;
    g_wo[o] = h; g_wo[WOTOT + o] = l;
}

// ---------------------------------------------------------------------------
// Kernel 1: fused QKV projection, fp16x2 HMMA + ldmatrix, cp.async 2-buf.
// grid = (64, 36), block = 256 (8 warps 4x2), CTA tile 128x64, k-chunk 32.
// ---------------------------------------------------------------------------
__global__ __launch_bounds__(256) void qkv_gemm(
    const float* __restrict__ bq, const float* __restrict__ bk,
    const float* __restrict__ bv)
{
    __shared__ __align__(16) uint32_t smq[10240];

    const int tid = threadIdx.x, lane = tid & 31, w = tid >> 5;
    const int wy = w >> 1, wx = w & 1;
    const int lr = lane & 7, lm = lane >> 3;
    const int row0 = blockIdx.x * 128;
    const int mh = blockIdx.y, m = mh / 12, h = mh % 12;
    const float* bias = (m == 0) ? bq : (m == 1) ? bk : bv;
    const float* bh = bias + h * 64;
    const uint32_t* w_h = g_wqkv + (size_t)mh * 64 * 384;
    const uint32_t* w_l = g_wqkv + WQKVTOT + (size_t)mh * 64 * 384;

    // Per-lane ldmatrix offsets (u32 units, stride 20)
    const int aoff = (wy * 32 + (lm & 1) * 8 + lr) * 20 + (lm >> 1) * 4;
    const int boff = (wx * 32 + (lm >> 1) * 8 + lr) * 20 + (lm & 1) * 4;
    const uint32_t smq_b = s2u(smq);

    auto load_chunk = [&](int ck, int bf) {
        uint32_t* Ab = smq + bf * 2560;
        #pragma unroll
        for (int i = 0; i < 2; i++) {
            int u = tid + i * 256;
            int r = u >> 2, q4 = u & 3;
            CPA16(s2u(&Ab[r * 20 + 4 * q4]),
                  &g_xh[(size_t)(row0 + r) * 384 + ck * 16 + 4 * q4]);
        }
        uint32_t* Bb = smq + 5120 + bf * 2560;
        int r = tid >> 2, q4 = tid & 3;
        CPA16(s2u(&Bb[r * 20 + 4 * q4]), &w_h[(size_t)r * 384 + ck * 16 + 4 * q4]);
        CPA16(s2u(&Bb[1280 + r * 20 + 4 * q4]), &w_l[(size_t)r * 384 + ck * 16 + 4 * q4]);
    };

    float acc[2][4][4] = {};
    load_chunk(0, 0); CPC();

    for (int ck = 0; ck < 24; ck++) {
        const int bf = ck & 1;
        if (ck < 23) { load_chunk(ck + 1, 1 - bf); CPC(); CPW1(); }
        else         { CPW0(); }
        __syncthreads();

        const uint32_t abase = smq_b + (bf * 2560) * 4;
        const uint32_t bbase = smq_b + (5120 + bf * 2560) * 4;
        #pragma unroll
        for (int kk = 0; kk < 2; kk++) {
            uint32_t a[2][4];
            #pragma unroll
            for (int mi = 0; mi < 2; mi++)
                LDSM4(a[mi][0], a[mi][1], a[mi][2], a[mi][3],
                      abase + (aoff + mi * 320 + kk * 8) * 4);
            #pragma unroll
            for (int np = 0; np < 2; np++) {
                uint32_t h0, h1, h2, h3, l0, l1, l2, l3;
                LDSM4(h0, h1, h2, h3, bbase + (boff + np * 320 + kk * 8) * 4);
                LDSM4(l0, l1, l2, l3, bbase + 5120 + (boff + np * 320 + kk * 8) * 4);
                uint32_t bh0[2] = {h0, h1}, bh1[2] = {h2, h3};
                uint32_t bl0[2] = {l0, l1}, bl1[2] = {l2, l3};
                #pragma unroll
                for (int mi = 0; mi < 2; mi++) {
                    mmah(acc[mi][2 * np],     a[mi], bh0);
                    mmah(acc[mi][2 * np],     a[mi], bl0);
                    mmah(acc[mi][2 * np + 1], a[mi], bh1);
                    mmah(acc[mi][2 * np + 1], a[mi], bl1);
                }
            }
        }
        __syncthreads();
    }

    if (m == 0) {
        #pragma unroll
        for (int mi = 0; mi < 2; mi++)
            #pragma unroll
            for (int ni = 0; ni < 4; ni++) {
                int col = wx * 32 + ni * 8 + 2 * (lane & 3);
                int cp = col >> 1;
                float b0 = bh[col], b1 = bh[col + 1];
                int rl = row0 + wy * 32 + mi * 16 + (lane >> 2);
                {
                    int bb = rl >> 11, n = rl & (S_ - 1);
                    g_q[((size_t)(bb * 12 + h) * 2048 + n) * 32 + cp] =
                        hpack((acc[mi][ni][0] + b0) * 0.125f,
                              (acc[mi][ni][1] + b1) * 0.125f);
                }
                {
                    int rh2 = rl + 8;
                    int bb = rh2 >> 11, n = rh2 & (S_ - 1);
                    g_q[((size_t)(bb * 12 + h) * 2048 + n) * 32 + cp] =
                        hpack((acc[mi][ni][2] + b0) * 0.125f,
                              (acc[mi][ni][3] + b1) * 0.125f);
                }
            }
    } else if (m == 1) {
        #pragma unroll
        for (int mi = 0; mi < 2; mi++)
            #pragma unroll
            for (int ni = 0; ni < 4; ni++) {
                int col = wx * 32 + ni * 8 + 2 * (lane & 3);
                int cp = col >> 1;
                float b0 = bh[col], b1 = bh[col + 1];
                int rl = row0 + wy * 32 + mi * 16 + (lane >> 2);
                uint32_t hh, ll;
                {
                    int bb = rl >> 11, n = rl & (S_ - 1);
                    size_t o = ((size_t)(bb * 12 + h) * 2048 + n) * 32 + cp;
                    hsplit2(acc[mi][ni][0] + b0, acc[mi][ni][1] + b1, hh, ll);
                    g_k[o] = hh; g_k[QTOT + o] = ll;
                }
                {
                    int rh2 = rl + 8;
                    int bb = rh2 >> 11, n = rh2 & (S_ - 1);
                    size_t o = ((size_t)(bb * 12 + h) * 2048 + n) * 32 + cp;
                    hsplit2(acc[mi][ni][2] + b0, acc[mi][ni][3] + b1, hh, ll);
                    g_k[o] = hh; g_k[QTOT + o] = ll;
                }
            }
    } else {
        const int s1 = (lane >> 2) & 1;
        #pragma unroll
        for (int mi = 0; mi < 2; mi++)
            #pragma unroll
            for (int ni = 0; ni < 4; ni++) {
                int col = wx * 32 + ni * 8 + 2 * (lane & 3);
                float b0 = bh[col], b1 = bh[col + 1];
                float v0 = acc[mi][ni][0] + b0, v1 = acc[mi][ni][1] + b1;
                float v2 = acc[mi][ni][2] + b0, v3 = acc[mi][ni][3] + b1;
                float p0 = __shfl_xor_sync(0xffffffffu, v0, 4);
                float p1 = __shfl_xor_sync(0xffffffffu, v1, 4);
                float p2 = __shfl_xor_sync(0xffffffffu, v2, 4);
                float p3 = __shfl_xor_sync(0xffffffffu, v3, 4);
                int e = col + s1;
                float fA = s1 ? p1 : v0;
                float sA = s1 ? v1 : p0;
                float fB = s1 ? p3 : v2;
                float sB = s1 ? v3 : p2;
                int rl = row0 + wy * 32 + mi * 16 + (lane >> 2);
                int bb = rl >> 11, n = rl & (S_ - 1);
                int np = n >> 1;
                size_t base = ((size_t)(bb * 12 + h) * 64 + e) * 1024;
                uint32_t hh, ll;
                hsplit2(fA, sA, hh, ll);
                g_vt[base + np] = hh;      g_vt[VTOT + base + np] = ll;
                hsplit2(fB, sB, hh, ll);
                g_vt[base + np + 4] = hh;  g_vt[VTOT + base + np + 4] = ll;
            }
    }
}

// ---------------------------------------------------------------------------
// Kernel 2: flash attention, fp16x2 + ldmatrix, cp.async 2-buf KV tiles.
// grid = (16, 12, 4), block = 256. Each warp owns 16 q rows.
// ---------------------------------------------------------------------------
__global__ __launch_bounds__(256) void flash_attn()
{
    extern __shared__ __align__(16) uint32_t sm2[];
    const int tid = threadIdx.x, lane = tid & 31, w = tid >> 5;
    const int lr = lane & 7, lm = lane >> 3;
    const int n0 = blockIdx.x * 128;
    const int h = blockIdx.y, b = blockIdx.z;
    const size_t qb = (size_t)(b * 12 + h) * 2048 * 32;
    const size_t vb = (size_t)(b * 12 + h) * 64 * 1024;
    const uint32_t sm_b = s2u(sm2);

    // Stage Q (plain fp16) into sm2[0..4608)
    #pragma unroll
    for (int i = 0; i < 4; i++) {
        int u = tid + i * 256;
        int r = u >> 3, q4 = u & 7;
        *(uint4*)&sm2[r * 36 + 4 * q4] =
            *(const uint4*)&g_q[qb + (size_t)(n0 + r) * 32 + 4 * q4];
    }
    __syncthreads();

    uint32_t qa[4][4];
    {
        // A-frag ldmatrix: rows w*16 + (lm&1)*8 + lr, col (lm>>1)*4
        const int qoff = (w * 16 + (lm & 1) * 8 + lr) * 36 + (lm >> 1) * 4;
        #pragma unroll
        for (int kk = 0; kk < 4; kk++)
            LDSM4(qa[kk][0], qa[kk][1], qa[kk][2], qa[kk][3],
                  sm_b + (qoff + kk * 8) * 4);
    }
    __syncthreads();   // Q stage area now reusable as buf0

    // Per-lane B-frag ldmatrix offset (stride 36)
    const int koff = ((lm >> 1) * 8 + lr) * 36 + (lm & 1) * 4;

    auto load_tile = [&](int t, int bf) {
        uint32_t* base = sm2 + bf * 9216;
        #pragma unroll
        for (int i = 0; i < 2; i++) {
            int u = tid + i * 256;
            int r = u >> 3, q4 = u & 7;
            size_t ks = qb + (size_t)(t * 64 + r) * 32 + 4 * q4;
            CPA16(s2u(&base[r * 36 + 4 * q4]),        &g_k[ks]);
            CPA16(s2u(&base[2304 + r * 36 + 4 * q4]), &g_k[QTOT + ks]);
            size_t vs = vb + (size_t)r * 1024 + t * 32 + 4 * q4;
            CPA16(s2u(&base[4608 + r * 36 + 4 * q4]), &g_vt[vs]);
            CPA16(s2u(&base[6912 + r * 36 + 4 * q4]), &g_vt[VTOT + vs]);
        }
    };

    float o[8][4] = {};
    float m_lo = -INFINITY, m_hi = -INFINITY;
    float l_lo = 0.f, l_hi = 0.f;

    load_tile(0, 0); CPC();

    for (int t = 0; t < 32; t++) {
        const int bf = t & 1;
        if (t < 31) { load_tile(t + 1, 1 - bf); CPC(); CPW1(); }
        else        { CPW0(); }
        __syncthreads();

        const uint32_t khb = sm_b + (bf * 9216) * 4;
        const uint32_t klb = khb + 2304 * 4;
        const uint32_t vhb = khb + 4608 * 4;
        const uint32_t vlb = khb + 6912 * 4;

        // S = Q K^T
        float s[8][4] = {};
        #pragma unroll
        for (int kk = 0; kk < 4; kk++) {
            #pragma unroll
            for (int np = 0; np < 4; np++) {
                uint32_t h0, h1, h2, h3, l0, l1, l2, l3;
                LDSM4(h0, h1, h2, h3, khb + (koff + np * 576 + kk * 8) * 4);
                LDSM4(l0, l1, l2, l3, klb + (koff + np * 576 + kk * 8) * 4);
                uint32_t bh0[2] = {h0, h1}, bh1[2] = {h2, h3};
                uint32_t bl0[2] = {l0, l1}, bl1[2] = {l2, l3};
                mmah(s[2 * np],     qa[kk], bh0);
                mmah(s[2 * np],     qa[kk], bl0);
                mmah(s[2 * np + 1], qa[kk], bh1);
                mmah(s[2 * np + 1], qa[kk], bl1);
            }
        }

        // Online softmax (warp-local, quad shfl)
        float mx_lo = -INFINITY, mx_hi = -INFINITY;
        #pragma unroll
        for (int ni = 0; ni < 8; ni++) {
            mx_lo = fmaxf(mx_lo, fmaxf(s[ni][0], s[ni][1]));
            mx_hi = fmaxf(mx_hi, fmaxf(s[ni][2], s[ni][3]));
        }
        mx_lo = fmaxf(mx_lo, __shfl_xor_sync(0xffffffffu, mx_lo, 1));
        mx_lo = fmaxf(mx_lo, __shfl_xor_sync(0xffffffffu, mx_lo, 2));
        mx_hi = fmaxf(mx_hi, __shfl_xor_sync(0xffffffffu, mx_hi, 1));
        mx_hi = fmaxf(mx_hi, __shfl_xor_sync(0xffffffffu, mx_hi, 2));

        float mn_lo = fmaxf(m_lo, mx_lo);
        float mn_hi = fmaxf(m_hi, mx_hi);
        float corr_lo = __expf(m_lo - mn_lo);
        float corr_hi = __expf(m_hi - mn_hi);

        float sum_lo = 0.f, sum_hi = 0.f;
        #pragma unroll
        for (int ni = 0; ni < 8; ni++) {
            s[ni][0] = __expf(s[ni][0] - mn_lo);
            s[ni][1] = __expf(s[ni][1] - mn_lo);
            s[ni][2] = __expf(s[ni][2] - mn_hi);
            s[ni][3] = __expf(s[ni][3] - mn_hi);
            sum_lo += s[ni][0] + s[ni][1];
            sum_hi += s[ni][2] + s[ni][3];
        }
        sum_lo += __shfl_xor_sync(0xffffffffu, sum_lo, 1);
        sum_lo += __shfl_xor_sync(0xffffffffu, sum_lo, 2);
        sum_hi += __shfl_xor_sync(0xffffffffu, sum_hi, 1);
        sum_hi += __shfl_xor_sync(0xffffffffu, sum_hi, 2);

        l_lo = l_lo * corr_lo + sum_lo;  m_lo = mn_lo;
        l_hi = l_hi * corr_hi + sum_hi;  m_hi = mn_hi;

        #pragma unroll
        for (int ni = 0; ni < 8; ni++) {
            o[ni][0] *= corr_lo; o[ni][1] *= corr_lo;
            o[ni][2] *= corr_hi; o[ni][3] *= corr_hi;
        }

        // O += P V
        #pragma unroll
        for (int j = 0; j < 4; j++) {
            uint32_t ph[4];
            ph[0] = hpack(s[2*j][0],   s[2*j][1]);
            ph[1] = hpack(s[2*j][2],   s[2*j][3]);
            ph[2] = hpack(s[2*j+1][0], s[2*j+1][1]);
            ph[3] = hpack(s[2*j+1][2], s[2*j+1][3]);
            #pragma unroll
            for (int np = 0; np < 4; np++) {
                uint32_t h0, h1, h2, h3, l0, l1, l2, l3;
                LDSM4(h0, h1, h2, h3, vhb + (koff + np * 576 + j * 8) * 4);
                LDSM4(l0, l1, l2, l3, vlb + (koff + np * 576 + j * 8) * 4);
                uint32_t bh0[2] = {h0, h1}, bh1[2] = {h2, h3};
                uint32_t bl0[2] = {l0, l1}, bl1[2] = {l2, l3};
                mmah(o[2 * np],     ph, bh0);
                mmah(o[2 * np],     ph, bl0);
                mmah(o[2 * np + 1], ph, bh1);
                mmah(o[2 * np + 1], ph, bl1);
            }
        }
        __syncthreads();
    }

    // ctx: plain fp16 packed [row][384]
    float inv_lo = 1.0f / l_lo, inv_hi = 1.0f / l_hi;
    int rl = n0 + w * 16 + (lane >> 2);
    #pragma unroll
    for (int ni = 0; ni < 8; ni++) {
        int cp = h * 32 + ni * 4 + (lane & 3);
        g_ch[(size_t)(b * 2048 + rl) * 384 + cp] =
            hpack(o[ni][0] * inv_lo, o[ni][1] * inv_lo);
        g_ch[(size_t)(b * 2048 + rl + 8) * 384 + cp] =
            hpack(o[ni][2] * inv_hi, o[ni][3] * inv_hi);
    }
}

// ---------------------------------------------------------------------------
// Kernel 3: output projection, fp16x2 + ldmatrix, cp.async 2-buf.
// grid = (64, 12), block = 256. fp32 out + bias.
// ---------------------------------------------------------------------------
__global__ __launch_bounds__(256) void out_gemm(
    const float* __restrict__ bo, float* __restrict__ out)
{
    __shared__ __align__(16) uint32_t smq[10240];

    const int tid = threadIdx.x, lane = tid & 31, w = tid >> 5;
    const int wy = w >> 1, wx = w & 1;
    const int lr = lane & 7, lm = lane >> 3;
    const int row0 = blockIdx.x * 128;
    const int col0 = blockIdx.y * 64;
    const uint32_t* w_h = g_wo + (size_t)col0 * 384;
    const uint32_t* w_l = g_wo + WOTOT + (size_t)col0 * 384;

    const int aoff = (wy * 32 + (lm & 1) * 8 + lr) * 20 + (lm >> 1) * 4;
    const int boff = (wx * 32 + (lm >> 1) * 8 + lr) * 20 + (lm & 1) * 4;
    const uint32_t smq_b = s2u(smq);

    auto load_chunk = [&](int ck, int bf) {
        uint32_t* Ab = smq + bf * 2560;
        #pragma unroll
        for (int i = 0; i < 2; i++) {
            int u = tid + i * 256;
            int r = u >> 2, q4 = u & 3;
            CPA16(s2u(&Ab[r * 20 + 4 * q4]),
                  &g_ch[(size_t)(row0 + r) * 384 + ck * 16 + 4 * q4]);
        }
        uint32_t* Bb = smq + 5120 + bf * 2560;
        int r = tid >> 2, q4 = tid & 3;
        CPA16(s2u(&Bb[r * 20 + 4 * q4]), &w_h[(size_t)r * 384 + ck * 16 + 4 * q4]);
        CPA16(s2u(&Bb[1280 + r * 20 + 4 * q4]), &w_l[(size_t)r * 384 + ck * 16 + 4 * q4]);
    };

    float acc[2][4][4] = {};
    load_chunk(0, 0); CPC();

    for (int ck = 0; ck < 24; ck++) {
        const int bf = ck & 1;
        if (ck < 23) { load_chunk(ck + 1, 1 - bf); CPC(); CPW1(); }
        else         { CPW0(); }
        __syncthreads();

        const uint32_t abase = smq_b + (bf * 2560) * 4;
        const uint32_t bbase = smq_b + (5120 + bf * 2560) * 4;
        #pragma unroll
        for (int kk = 0; kk < 2; kk++) {
            uint32_t a[2][4];
            #pragma unroll
            for (int mi = 0; mi < 2; mi++)
                LDSM4(a[mi][0], a[mi][1], a[mi][2], a[mi][3],
                      abase + (aoff + mi * 320 + kk * 8) * 4);
            #pragma unroll
            for (int np = 0; np < 2; np++) {
                uint32_t h0, h1, h2, h3, l0, l1, l2, l3;
                LDSM4(h0, h1, h2, h3, bbase + (boff + np * 320 + kk * 8) * 4);
                LDSM4(l0, l1, l2, l3, bbase + 5120 + (boff + np * 320 + kk * 8) * 4);
                uint32_t bh0[2] = {h0, h1}, bh1[2] = {h2, h3};
                uint32_t bl0[2] = {l0, l1}, bl1[2] = {l2, l3};
                #pragma unroll
                for (int mi = 0; mi < 2; mi++) {
                    mmah(acc[mi][2 * np],     a[mi], bh0);
                    mmah(acc[mi][2 * np],     a[mi], bl0);
                    mmah(acc[mi][2 * np + 1], a[mi], bh1);
                    mmah(acc[mi][2 * np + 1], a[mi], bl1);
                }
            }
        }
        __syncthreads();
    }

    #pragma unroll
    for (int mi = 0; mi < 2; mi++)
        #pragma unroll
        for (int ni = 0; ni < 4; ni++) {
            int col = col0 + wx * 32 + ni * 8 + 2 * (lane & 3);
            float b0 = bo[col], b1 = bo[col + 1];
            int rl = row0 + wy * 32 + mi * 16 + (lane >> 2);
            float2 v0, v1;
            v0.x = acc[mi][ni][0] + b0;  v0.y = acc[mi][ni][1] + b1;
            v1.x = acc[mi][ni][2] + b0;  v1.y = acc[mi][ni][3] + b1;
            *(float2*)&out[(size_t)rl * D_ + col] = v0;
            *(float2*)&out[(size_t)(rl + 8) * D_ + col] = v1;
        }
}

// ---------------------------------------------------------------------------
extern "C" void kernel_launch(void* const* d_in, const int* in_sizes, int n_in,
                              void* d_out, int out_size)
{
    const float* x  = (const float*)d_in[0];
    const float* Wq = (const float*)d_in[1];
    const float* bq = (const float*)d_in[2];
    const float* Wk = (const float*)d_in[3];
    const float* bk = (const float*)d_in[4];
    const float* Wv = (const float*)d_in[5];
    const float* bv = (const float*)d_in[6];
    const float* Wo = (const float*)d_in[7];
    const float* bo = (const float*)d_in[8];
    float* out = (float*)d_out;

    const int flash_smem = 18432 * (int)sizeof(uint32_t);   // 73,728 B
    cudaFuncSetAttribute(flash_attn,
                         cudaFuncAttributeMaxDynamicSharedMemorySize, flash_smem);

    split_x_kernel<<<(int)(XTOT / 256), 256>>>(x);
    split_wqkv_kernel<<<(int)(WQKVTOT / 256), 256>>>(Wq, Wk, Wv);
    split_wo_kernel<<<(int)(WOTOT / 256), 256>>>(Wo);

    dim3 g1(64, 36);
    qkv_gemm<<<g1, 256>>>(bq, bk, bv);

    dim3 g2(16, 12, 4);
    flash_attn<<<g2, 256, flash_smem>>>();

    dim3 g3(64, 12);
    out_gemm<<<g3, 256>>>(bo, out);
}

// round 16
// speedup vs baseline: 7.1926x; 1.0403x over previous
#include <cuda_runtime.h>
#include <cuda_fp16.h>
#include <math.h>
#include <stdint.h>

#define B_ 4
#define S_ 2048
#define D_ 768
#define H_ 12
#define DH_ 64

// Packed-u32 (fp16 pair) array sizes
#define XTOT    ((size_t)8192 * 384)      // x / ctx: [row][384 kpairs]
#define WQKVTOT ((size_t)36 * 64 * 384)   // [m*12+h][n][384]  (hi/lo planes)
#define WOTOT   ((size_t)768 * 384)       // [n][384]          (hi/lo planes)
#define QTOT    ((size_t)48 * 2048 * 32)  // q (single) / k (hi/lo): [b*12+h][n][32]
#define VTOT    ((size_t)48 * 64 * 1024)  // vt (hi/lo): [b*12+h][e][1024 token-pairs]

// q carries 0.125 * log2(e) so softmax uses raw ex2
#define QSCALE 0.1803368801111137f

__device__ __align__(16) uint32_t g_xh[XTOT];
__device__ __align__(16) uint32_t g_wqkv[2 * WQKVTOT];
__device__ __align__(16) uint32_t g_wo[2 * WOTOT];
__device__ __align__(16) uint32_t g_q[QTOT];
__device__ __align__(16) uint32_t g_k[2 * QTOT];
__device__ __align__(16) uint32_t g_vt[2 * VTOT];
__device__ __align__(16) uint32_t g_ch[XTOT];

// ---------------------------------------------------------------------------
__device__ __forceinline__ uint32_t hpack(float a, float b) {
    __half2 h = __floats2half2_rn(a, b);
    return *reinterpret_cast<uint32_t*>(&h);
}
__device__ __forceinline__ void hsplit2(float a, float b, uint32_t& h, uint32_t& l) {
    __half2 hh = __floats2half2_rn(a, b);
    float2 f = __half22float2(hh);
    h = *reinterpret_cast<uint32_t*>(&hh);
    l = hpack(a - f.x, b - f.y);
}
__device__ __forceinline__ float ex2(float x) {
    float r; asm("ex2.approx.f32 %0, %1;" : "=f"(r) : "f"(x)); return r;
}
__device__ __forceinline__ void mmah(float d[4], const uint32_t a[4], const uint32_t b[2]) {
    asm volatile(
        "mma.sync.aligned.m16n8k16.row.col.f32.f16.f16.f32 "
        "{%0,%1,%2,%3}, {%4,%5,%6,%7}, {%8,%9}, {%0,%1,%2,%3};"
        : "+f"(d[0]), "+f"(d[1]), "+f"(d[2]), "+f"(d[3])
        : "r"(a[0]), "r"(a[1]), "r"(a[2]), "r"(a[3]), "r"(b[0]), "r"(b[1]));
}
__device__ __forceinline__ uint32_t s2u(const void* p) {
    return (uint32_t)__cvta_generic_to_shared(p);
}
#define LDSM4(R0, R1, R2, R3, ADDR) \
    asm volatile("ldmatrix.sync.aligned.m8n8.x4.shared.b16 {%0,%1,%2,%3}, [%4];" \
                 : "=r"(R0), "=r"(R1), "=r"(R2), "=r"(R3) : "r"(ADDR))
#define CPA16(dst, src) \
    asm volatile("cp.async.cg.shared.global [%0], [%1], 16;" :: "r"(dst), "l"(src) : "memory")
#define CPC() asm volatile("cp.async.commit_group;" ::: "memory")
#define CPW1() asm volatile("cp.async.wait_group 1;" ::: "memory")
#define CPW0() asm volatile("cp.async.wait_group 0;" ::: "memory")

// ---------------------------------------------------------------------------
// Prep kernels
// ---------------------------------------------------------------------------
__global__ void split_x_kernel(const float* __restrict__ x) {
    size_t u = (size_t)blockIdx.x * 256 + threadIdx.x;
    float2 v = *(const float2*)&x[2 * u];
    g_xh[u] = hpack(v.x, v.y);
}

__global__ void split_wqkv_kernel(const float* __restrict__ Wq,
                                  const float* __restrict__ Wk,
                                  const float* __restrict__ Wv) {
    size_t u = (size_t)blockIdx.x * 256 + threadIdx.x;
    int n = u & 63;
    size_t t = u >> 6;
    int kp = (int)(t % 384);
    int mh = (int)(t / 384);
    const float* W = (mh < 12) ? Wq : (mh < 24) ? Wk : Wv;
    const float* base = W + (size_t)(mh % 12) * D_ * DH_;
    float a = base[(size_t)(2 * kp) * 64 + n];
    float b = base[(size_t)(2 * kp + 1) * 64 + n];
    uint32_t h, l; hsplit2(a, b, h, l);
    size_t o = ((size_t)mh * 64 + n) * 384 + kp;
    g_wqkv[o] = h; g_wqkv[WQKVTOT + o] = l;
}

__global__ void split_wo_kernel(const float* __restrict__ Wo) {
    size_t u = (size_t)blockIdx.x * 256 + threadIdx.x;
    int n = (int)(u % 768);
    int kp = (int)(u / 768);
    float a = Wo[(size_t)(2 * kp) * 768 + n];
    float b = Wo[(size_t)(2 * kp + 1) * 768 + n];
    uint32_t h, l; hsplit2(a, b, h, l);
    size_t o = (size_t)n * 384 + kp;
    g_wo[o] = h; g_wo[WOTOT + o] = l;
}

// ---------------------------------------------------------------------------
// Kernel 1: fused QKV projection, fp16x2 + ldmatrix, 3-stage cp.async.
// grid = (64, 36), block = 256 (8 warps 4x2), CTA tile 128x64, k-chunk 32.
// Dynamic smem: 3 stages x (A 2560 + B 2560) u32 = 61440 B.
// ---------------------------------------------------------------------------
__global__ __launch_bounds__(256) void qkv_gemm(
    const float* __restrict__ bq, const float* __restrict__ bk,
    const float* __restrict__ bv)
{
    extern __shared__ __align__(16) uint32_t smq[];

    const int tid = threadIdx.x, lane = tid & 31, w = tid >> 5;
    const int wy = w >> 1, wx = w & 1;
    const int lr = lane & 7, lm = lane >> 3;
    const int row0 = blockIdx.x * 128;
    const int mh = blockIdx.y, m = mh / 12, h = mh % 12;
    const float* bias = (m == 0) ? bq : (m == 1) ? bk : bv;
    const float* bh = bias + h * 64;
    const uint32_t* w_h = g_wqkv + (size_t)mh * 64 * 384;
    const uint32_t* w_l = g_wqkv + WQKVTOT + (size_t)mh * 64 * 384;

    const int aoff = (wy * 32 + (lm & 1) * 8 + lr) * 20 + (lm >> 1) * 4;
    const int boff = (wx * 32 + (lm >> 1) * 8 + lr) * 20 + (lm & 1) * 4;
    const uint32_t smq_b = s2u(smq);

    auto load_chunk = [&](int ck, int st) {
        uint32_t* Ab = smq + st * 5120;
        #pragma unroll
        for (int i = 0; i < 2; i++) {
            int u = tid + i * 256;
            int r = u >> 2, q4 = u & 3;
            CPA16(s2u(&Ab[r * 20 + 4 * q4]),
                  &g_xh[(size_t)(row0 + r) * 384 + ck * 16 + 4 * q4]);
        }
        uint32_t* Bb = Ab + 2560;
        int r = tid >> 2, q4 = tid & 3;
        CPA16(s2u(&Bb[r * 20 + 4 * q4]), &w_h[(size_t)r * 384 + ck * 16 + 4 * q4]);
        CPA16(s2u(&Bb[1280 + r * 20 + 4 * q4]), &w_l[(size_t)r * 384 + ck * 16 + 4 * q4]);
    };

    float acc[2][4][4] = {};
    load_chunk(0, 0); CPC();
    load_chunk(1, 1); CPC();

    for (int ck = 0; ck < 24; ck++) {
        const int st = ck % 3;
        if (ck < 22) CPW1(); else CPW0();
        __syncthreads();
        if (ck + 2 < 24) { load_chunk(ck + 2, (ck + 2) % 3); CPC(); }

        const uint32_t abase = smq_b + (st * 5120) * 4;
        const uint32_t bbase = abase + 2560 * 4;
        #pragma unroll
        for (int kk = 0; kk < 2; kk++) {
            uint32_t a[2][4];
            #pragma unroll
            for (int mi = 0; mi < 2; mi++)
                LDSM4(a[mi][0], a[mi][1], a[mi][2], a[mi][3],
                      abase + (aoff + mi * 320 + kk * 8) * 4);
            #pragma unroll
            for (int np = 0; np < 2; np++) {
                uint32_t h0, h1, h2, h3, l0, l1, l2, l3;
                LDSM4(h0, h1, h2, h3, bbase + (boff + np * 320 + kk * 8) * 4);
                LDSM4(l0, l1, l2, l3, bbase + 5120 + (boff + np * 320 + kk * 8) * 4);
                uint32_t bh0[2] = {h0, h1}, bh1[2] = {h2, h3};
                uint32_t bl0[2] = {l0, l1}, bl1[2] = {l2, l3};
                #pragma unroll
                for (int mi = 0; mi < 2; mi++) {
                    mmah(acc[mi][2 * np],     a[mi], bh0);
                    mmah(acc[mi][2 * np],     a[mi], bl0);
                    mmah(acc[mi][2 * np + 1], a[mi], bh1);
                    mmah(acc[mi][2 * np + 1], a[mi], bl1);
                }
            }
        }
    }

    if (m == 0) {
        #pragma unroll
        for (int mi = 0; mi < 2; mi++)
            #pragma unroll
            for (int ni = 0; ni < 4; ni++) {
                int col = wx * 32 + ni * 8 + 2 * (lane & 3);
                int cp = col >> 1;
                float b0 = bh[col], b1 = bh[col + 1];
                int rl = row0 + wy * 32 + mi * 16 + (lane >> 2);
                {
                    int bb = rl >> 11, n = rl & (S_ - 1);
                    g_q[((size_t)(bb * 12 + h) * 2048 + n) * 32 + cp] =
                        hpack((acc[mi][ni][0] + b0) * QSCALE,
                              (acc[mi][ni][1] + b1) * QSCALE);
                }
                {
                    int rh2 = rl + 8;
                    int bb = rh2 >> 11, n = rh2 & (S_ - 1);
                    g_q[((size_t)(bb * 12 + h) * 2048 + n) * 32 + cp] =
                        hpack((acc[mi][ni][2] + b0) * QSCALE,
                              (acc[mi][ni][3] + b1) * QSCALE);
                }
            }
    } else if (m == 1) {
        #pragma unroll
        for (int mi = 0; mi < 2; mi++)
            #pragma unroll
            for (int ni = 0; ni < 4; ni++) {
                int col = wx * 32 + ni * 8 + 2 * (lane & 3);
                int cp = col >> 1;
                float b0 = bh[col], b1 = bh[col + 1];
                int rl = row0 + wy * 32 + mi * 16 + (lane >> 2);
                uint32_t hh, ll;
                {
                    int bb = rl >> 11, n = rl & (S_ - 1);
                    size_t o = ((size_t)(bb * 12 + h) * 2048 + n) * 32 + cp;
                    hsplit2(acc[mi][ni][0] + b0, acc[mi][ni][1] + b1, hh, ll);
                    g_k[o] = hh; g_k[QTOT + o] = ll;
                }
                {
                    int rh2 = rl + 8;
                    int bb = rh2 >> 11, n = rh2 & (S_ - 1);
                    size_t o = ((size_t)(bb * 12 + h) * 2048 + n) * 32 + cp;
                    hsplit2(acc[mi][ni][2] + b0, acc[mi][ni][3] + b1, hh, ll);
                    g_k[o] = hh; g_k[QTOT + o] = ll;
                }
            }
    } else {
        const int s1 = (lane >> 2) & 1;
        #pragma unroll
        for (int mi = 0; mi < 2; mi++)
            #pragma unroll
            for (int ni = 0; ni < 4; ni++) {
                int col = wx * 32 + ni * 8 + 2 * (lane & 3);
                float b0 = bh[col], b1 = bh[col + 1];
                float v0 = acc[mi][ni][0] + b0, v1 = acc[mi][ni][1] + b1;
                float v2 = acc[mi][ni][2] + b0, v3 = acc[mi][ni][3] + b1;
                float p0 = __shfl_xor_sync(0xffffffffu, v0, 4);
                float p1 = __shfl_xor_sync(0xffffffffu, v1, 4);
                float p2 = __shfl_xor_sync(0xffffffffu, v2, 4);
                float p3 = __shfl_xor_sync(0xffffffffu, v3, 4);
                int e = col + s1;
                float fA = s1 ? p1 : v0;
                float sA = s1 ? v1 : p0;
                float fB = s1 ? p3 : v2;
                float sB = s1 ? v3 : p2;
                int rl = row0 + wy * 32 + mi * 16 + (lane >> 2);
                int bb = rl >> 11, n = rl & (S_ - 1);
                int np = n >> 1;
                size_t base = ((size_t)(bb * 12 + h) * 64 + e) * 1024;
                uint32_t hh, ll;
                hsplit2(fA, sA, hh, ll);
                g_vt[base + np] = hh;      g_vt[VTOT + base + np] = ll;
                hsplit2(fB, sB, hh, ll);
                g_vt[base + np + 4] = hh;  g_vt[VTOT + base + np + 4] = ll;
            }
    }
}

// ---------------------------------------------------------------------------
// Kernel 2: flash attention, fp16x2 + ldmatrix, 3-stage cp.async KV tiles.
// grid = (16, 12, 4), block = 256. Dynamic smem: 3 x 9216 u32 = 110,592 B.
// ---------------------------------------------------------------------------
__global__ __launch_bounds__(256) void flash_attn()
{
    extern __shared__ __align__(16) uint32_t sm2[];
    const int tid = threadIdx.x, lane = tid & 31, w = tid >> 5;
    const int lr = lane & 7, lm = lane >> 3;
    const int n0 = blockIdx.x * 128;
    const int h = blockIdx.y, b = blockIdx.z;
    const size_t qb = (size_t)(b * 12 + h) * 2048 * 32;
    const size_t vb = (size_t)(b * 12 + h) * 64 * 1024;
    const uint32_t sm_b = s2u(sm2);

    auto load_tile = [&](int t, int st) {
        uint32_t* base = sm2 + st * 9216;
        #pragma unroll
        for (int i = 0; i < 2; i++) {
            int u = tid + i * 256;
            int r = u >> 3, q4 = u & 7;
            size_t ks = qb + (size_t)(t * 64 + r) * 32 + 4 * q4;
            CPA16(s2u(&base[r * 36 + 4 * q4]),        &g_k[ks]);
            CPA16(s2u(&base[2304 + r * 36 + 4 * q4]), &g_k[QTOT + ks]);
            size_t vs = vb + (size_t)r * 1024 + t * 32 + 4 * q4;
            CPA16(s2u(&base[4608 + r * 36 + 4 * q4]), &g_vt[vs]);
            CPA16(s2u(&base[6912 + r * 36 + 4 * q4]), &g_vt[VTOT + vs]);
        }
    };

    load_tile(0, 0); CPC();
    load_tile(1, 1); CPC();

    // Stage Q (plain fp16) into stage-2 area; read fragments; reclaimed at t=0 sync.
    uint32_t* Qs = sm2 + 2 * 9216;
    #pragma unroll
    for (int i = 0; i < 4; i++) {
        int u = tid + i * 256;
        int r = u >> 3, q4 = u & 7;
        *(uint4*)&Qs[r * 36 + 4 * q4] =
            *(const uint4*)&g_q[qb + (size_t)(n0 + r) * 32 + 4 * q4];
    }
    __syncthreads();

    uint32_t qa[4][4];
    {
        const int qoff = 2 * 9216 + (w * 16 + (lm & 1) * 8 + lr) * 36 + (lm >> 1) * 4;
        #pragma unroll
        for (int kk = 0; kk < 4; kk++)
            LDSM4(qa[kk][0], qa[kk][1], qa[kk][2], qa[kk][3],
                  sm_b + (qoff + kk * 8) * 4);
    }

    const int koff = ((lm >> 1) * 8 + lr) * 36 + (lm & 1) * 4;

    float o[8][4] = {};
    float m_lo = -INFINITY, m_hi = -INFINITY;
    float l_lo = 0.f, l_hi = 0.f;

    for (int t = 0; t < 32; t++) {
        const int st = t % 3;
        if (t < 30) CPW1(); else CPW0();
        __syncthreads();
        if (t + 2 < 32) { load_tile(t + 2, (t + 2) % 3); CPC(); }

        const uint32_t khb = sm_b + (st * 9216) * 4;
        const uint32_t klb = khb + 2304 * 4;
        const uint32_t vhb = khb + 4608 * 4;
        const uint32_t vlb = khb + 6912 * 4;

        // S = Q K^T (log2-domain scores; QSCALE carries log2e)
        float s[8][4] = {};
        #pragma unroll
        for (int kk = 0; kk < 4; kk++) {
            #pragma unroll
            for (int np = 0; np < 4; np++) {
                uint32_t h0, h1, h2, h3, l0, l1, l2, l3;
                LDSM4(h0, h1, h2, h3, khb + (koff + np * 576 + kk * 8) * 4);
                LDSM4(l0, l1, l2, l3, klb + (koff + np * 576 + kk * 8) * 4);
                uint32_t bh0[2] = {h0, h1}, bh1[2] = {h2, h3};
                uint32_t bl0[2] = {l0, l1}, bl1[2] = {l2, l3};
                mmah(s[2 * np],     qa[kk], bh0);
                mmah(s[2 * np],     qa[kk], bl0);
                mmah(s[2 * np + 1], qa[kk], bh1);
                mmah(s[2 * np + 1], qa[kk], bl1);
            }
        }

        // Online softmax, base-2 (warp-local, quad shfl)
        float mx_lo = -INFINITY, mx_hi = -INFINITY;
        #pragma unroll
        for (int ni = 0; ni < 8; ni++) {
            mx_lo = fmaxf(mx_lo, fmaxf(s[ni][0], s[ni][1]));
            mx_hi = fmaxf(mx_hi, fmaxf(s[ni][2], s[ni][3]));
        }
        mx_lo = fmaxf(mx_lo, __shfl_xor_sync(0xffffffffu, mx_lo, 1));
        mx_lo = fmaxf(mx_lo, __shfl_xor_sync(0xffffffffu, mx_lo, 2));
        mx_hi = fmaxf(mx_hi, __shfl_xor_sync(0xffffffffu, mx_hi, 1));
        mx_hi = fmaxf(mx_hi, __shfl_xor_sync(0xffffffffu, mx_hi, 2));

        float mn_lo = fmaxf(m_lo, mx_lo);
        float mn_hi = fmaxf(m_hi, mx_hi);
        float corr_lo = ex2(m_lo - mn_lo);
        float corr_hi = ex2(m_hi - mn_hi);

        float sum_lo = 0.f, sum_hi = 0.f;
        #pragma unroll
        for (int ni = 0; ni < 8; ni++) {
            s[ni][0] = ex2(s[ni][0] - mn_lo);
            s[ni][1] = ex2(s[ni][1] - mn_lo);
            s[ni][2] = ex2(s[ni][2] - mn_hi);
            s[ni][3] = ex2(s[ni][3] - mn_hi);
            sum_lo += s[ni][0] + s[ni][1];
            sum_hi += s[ni][2] + s[ni][3];
        }
        sum_lo += __shfl_xor_sync(0xffffffffu, sum_lo, 1);
        sum_lo += __shfl_xor_sync(0xffffffffu, sum_lo, 2);
        sum_hi += __shfl_xor_sync(0xffffffffu, sum_hi, 1);
        sum_hi += __shfl_xor_sync(0xffffffffu, sum_hi, 2);

        l_lo = l_lo * corr_lo + sum_lo;  m_lo = mn_lo;
        l_hi = l_hi * corr_hi + sum_hi;  m_hi = mn_hi;

        #pragma unroll
        for (int ni = 0; ni < 8; ni++) {
            o[ni][0] *= corr_lo; o[ni][1] *= corr_lo;
            o[ni][2] *= corr_hi; o[ni][3] *= corr_hi;
        }

        // O += P V
        #pragma unroll
        for (int j = 0; j < 4; j++) {
            uint32_t ph[4];
            ph[0] = hpack(s[2*j][0],   s[2*j][1]);
            ph[1] = hpack(s[2*j][2],   s[2*j][3]);
            ph[2] = hpack(s[2*j+1][0], s[2*j+1][1]);
            ph[3] = hpack(s[2*j+1][2], s[2*j+1][3]);
            #pragma unroll
            for (int np = 0; np < 4; np++) {
                uint32_t h0, h1, h2, h3, l0, l1, l2, l3;
                LDSM4(h0, h1, h2, h3, vhb + (koff + np * 576 + j * 8) * 4);
                LDSM4(l0, l1, l2, l3, vlb + (koff + np * 576 + j * 8) * 4);
                uint32_t bh0[2] = {h0, h1}, bh1[2] = {h2, h3};
                uint32_t bl0[2] = {l0, l1}, bl1[2] = {l2, l3};
                mmah(o[2 * np],     ph, bh0);
                mmah(o[2 * np],     ph, bl0);
                mmah(o[2 * np + 1], ph, bh1);
                mmah(o[2 * np + 1], ph, bl1);
            }
        }
    }

    // ctx: plain fp16 packed [row][384]
    float inv_lo = 1.0f / l_lo, inv_hi = 1.0f / l_hi;
    int rl = n0 + w * 16 + (lane >> 2);
    #pragma unroll
    for (int ni = 0; ni < 8; ni++) {
        int cp = h * 32 + ni * 4 + (lane & 3);
        g_ch[(size_t)(b * 2048 + rl) * 384 + cp] =
            hpack(o[ni][0] * inv_lo, o[ni][1] * inv_lo);
        g_ch[(size_t)(b * 2048 + rl + 8) * 384 + cp] =
            hpack(o[ni][2] * inv_hi, o[ni][3] * inv_hi);
    }
}

// ---------------------------------------------------------------------------
// Kernel 3: output projection, fp16x2 + ldmatrix, 3-stage cp.async.
// grid = (64, 12), block = 256. fp32 out + bias. Dynamic smem 61,440 B.
// ---------------------------------------------------------------------------
__global__ __launch_bounds__(256) void out_gemm(
    const float* __restrict__ bo, float* __restrict__ out)
{
    extern __shared__ __align__(16) uint32_t smq[];

    const int tid = threadIdx.x, lane = tid & 31, w = tid >> 5;
    const int wy = w >> 1, wx = w & 1;
    const int lr = lane & 7, lm = lane >> 3;
    const int row0 = blockIdx.x * 128;
    const int col0 = blockIdx.y * 64;
    const uint32_t* w_h = g_wo + (size_t)col0 * 384;
    const uint32_t* w_l = g_wo + WOTOT + (size_t)col0 * 384;

    const int aoff = (wy * 32 + (lm & 1) * 8 + lr) * 20 + (lm >> 1) * 4;
    const int boff = (wx * 32 + (lm >> 1) * 8 + lr) * 20 + (lm & 1) * 4;
    const uint32_t smq_b = s2u(smq);

    auto load_chunk = [&](int ck, int st) {
        uint32_t* Ab = smq + st * 5120;
        #pragma unroll
        for (int i = 0; i < 2; i++) {
            int u = tid + i * 256;
            int r = u >> 2, q4 = u & 3;
            CPA16(s2u(&Ab[r * 20 + 4 * q4]),
                  &g_ch[(size_t)(row0 + r) * 384 + ck * 16 + 4 * q4]);
        }
        uint32_t* Bb = Ab + 2560;
        int r = tid >> 2, q4 = tid & 3;
        CPA16(s2u(&Bb[r * 20 + 4 * q4]), &w_h[(size_t)r * 384 + ck * 16 + 4 * q4]);
        CPA16(s2u(&Bb[1280 + r * 20 + 4 * q4]), &w_l[(size_t)r * 384 + ck * 16 + 4 * q4]);
    };

    float acc[2][4][4] = {};
    load_chunk(0, 0); CPC();
    load_chunk(1, 1); CPC();

    for (int ck = 0; ck < 24; ck++) {
        const int st = ck % 3;
        if (ck < 22) CPW1(); else CPW0();
        __syncthreads();
        if (ck + 2 < 24) { load_chunk(ck + 2, (ck + 2) % 3); CPC(); }

        const uint32_t abase = smq_b + (st * 5120) * 4;
        const uint32_t bbase = abase + 2560 * 4;
        #pragma unroll
        for (int kk = 0; kk < 2; kk++) {
            uint32_t a[2][4];
            #pragma unroll
            for (int mi = 0; mi < 2; mi++)
                LDSM4(a[mi][0], a[mi][1], a[mi][2], a[mi][3],
                      abase + (aoff + mi * 320 + kk * 8) * 4);
            #pragma unroll
            for (int np = 0; np < 2; np++) {
                uint32_t h0, h1, h2, h3, l0, l1, l2, l3;
                LDSM4(h0, h1, h2, h3, bbase + (boff + np * 320 + kk * 8) * 4);
                LDSM4(l0, l1, l2, l3, bbase + 5120 + (boff + np * 320 + kk * 8) * 4);
                uint32_t bh0[2] = {h0, h1}, bh1[2] = {h2, h3};
                uint32_t bl0[2] = {l0, l1}, bl1[2] = {l2, l3};
                #pragma unroll
                for (int mi = 0; mi < 2; mi++) {
                    mmah(acc[mi][2 * np],     a[mi], bh0);
                    mmah(acc[mi][2 * np],     a[mi], bl0);
                    mmah(acc[mi][2 * np + 1], a[mi], bh1);
                    mmah(acc[mi][2 * np + 1], a[mi], bl1);
                }
            }
        }
    }

    #pragma unroll
    for (int mi = 0; mi < 2; mi++)
        #pragma unroll
        for (int ni = 0; ni < 4; ni++) {
            int col = col0 + wx * 32 + ni * 8 + 2 * (lane & 3);
            float b0 = bo[col], b1 = bo[col + 1];
            int rl = row0 + wy * 32 + mi * 16 + (lane >> 2);
            float2 v0, v1;
            v0.x = acc[mi][ni][0] + b0;  v0.y = acc[mi][ni][1] + b1;
            v1.x = acc[mi][ni][2] + b0;  v1.y = acc[mi][ni][3] + b1;
            *(float2*)&out[(size_t)rl * D_ + col] = v0;
            *(float2*)&out[(size_t)(rl + 8) * D_ + col] = v1;
        }
}

// ---------------------------------------------------------------------------
extern "C" void kernel_launch(void* const* d_in, const int* in_sizes, int n_in,
                              void* d_out, int out_size)
{
    const float* x  = (const float*)d_in[0];
    const float* Wq = (const float*)d_in[1];
    const float* bq = (const float*)d_in[2];
    const float* Wk = (const float*)d_in[3];
    const float* bk = (const float*)d_in[4];
    const float* Wv = (const float*)d_in[5];
    const float* bv = (const float*)d_in[6];
    const float* Wo = (const float*)d_in[7];
    const float* bo = (const float*)d_in[8];
    float* out = (float*)d_out;

    const int gemm_smem  = 3 * 5120 * (int)sizeof(uint32_t);   // 61,440 B
    const int flash_smem = 3 * 9216 * (int)sizeof(uint32_t);   // 110,592 B
    cudaFuncSetAttribute(qkv_gemm,
                         cudaFuncAttributeMaxDynamicSharedMemorySize, gemm_smem);
    cudaFuncSetAttribute(out_gemm,
                         cudaFuncAttributeMaxDynamicSharedMemorySize, gemm_smem);
    cudaFuncSetAttribute(flash_attn,
                         cudaFuncAttributeMaxDynamicSharedMemorySize, flash_smem);

    split_x_kernel<<<(int)(XTOT / 256), 256>>>(x);
    split_wqkv_kernel<<<(int)(WQKVTOT / 256), 256>>>(Wq, Wk, Wv);
    split_wo_kernel<<<(int)(WOTOT / 256), 256>>>(Wo);

    dim3 g1(64, 36);
    qkv_gemm<<<g1, 256, gemm_smem>>>(bq, bk, bv);

    dim3 g2(16, 12, 4);
    flash_attn<<<g2, 256, flash_smem>>>();

    dim3 g3(64, 12);
    out_gemm<<<g3, 256, gemm_smem>>>(bo, out);
}

// round 17
// speedup vs baseline: 7.3444x; 1.0211x over previous
#include <cuda_runtime.h>
#include <cuda_fp16.h>
#include <math.h>
#include <stdint.h>

#define B_ 4
#define S_ 2048
#define D_ 768
#define H_ 12
#define DH_ 64

// Packed-u32 (fp16 pair) array sizes
#define XTOT    ((size_t)8192 * 384)      // x / ctx: [row][384 kpairs]
#define WQKVTOT ((size_t)36 * 64 * 384)   // [m*12+h][n][384]  (hi/lo planes)
#define WOTOT   ((size_t)768 * 384)       // [n][384]          (hi/lo planes)
#define QTOT    ((size_t)48 * 2048 * 32)  // q (single) / k (hi/lo): [b*12+h][n][32]
#define VTOT    ((size_t)48 * 64 * 1024)  // vt (hi/lo): [b*12+h][e][1024 token-pairs]

// q carries 0.125 * log2(e) so softmax uses raw ex2
#define QSCALE 0.1803368801111137f

__device__ __align__(16) uint32_t g_xh[XTOT];
__device__ __align__(16) uint32_t g_wqkv[2 * WQKVTOT];
__device__ __align__(16) uint32_t g_wo[2 * WOTOT];
__device__ __align__(16) uint32_t g_q[QTOT];
__device__ __align__(16) uint32_t g_k[2 * QTOT];
__device__ __align__(16) uint32_t g_vt[2 * VTOT];
__device__ __align__(16) uint32_t g_ch[XTOT];

// ---------------------------------------------------------------------------
__device__ __forceinline__ uint32_t hpack(float a, float b) {
    __half2 h = __floats2half2_rn(a, b);
    return *reinterpret_cast<uint32_t*>(&h);
}
__device__ __forceinline__ void hsplit2(float a, float b, uint32_t& h, uint32_t& l) {
    __half2 hh = __floats2half2_rn(a, b);
    float2 f = __half22float2(hh);
    h = *reinterpret_cast<uint32_t*>(&hh);
    l = hpack(a - f.x, b - f.y);
}
__device__ __forceinline__ float ex2(float x) {
    float r; asm("ex2.approx.f32 %0, %1;" : "=f"(r) : "f"(x)); return r;
}
__device__ __forceinline__ uint32_t ex2h2(uint32_t x) {
    uint32_t r; asm("ex2.approx.f16x2 %0, %1;" : "=r"(r) : "r"(x)); return r;
}
__device__ __forceinline__ void mmah(float d[4], const uint32_t a[4], const uint32_t b[2]) {
    asm volatile(
        "mma.sync.aligned.m16n8k16.row.col.f32.f16.f16.f32 "
        "{%0,%1,%2,%3}, {%4,%5,%6,%7}, {%8,%9}, {%0,%1,%2,%3};"
        : "+f"(d[0]), "+f"(d[1]), "+f"(d[2]), "+f"(d[3])
        : "r"(a[0]), "r"(a[1]), "r"(a[2]), "r"(a[3]), "r"(b[0]), "r"(b[1]));
}
__device__ __forceinline__ uint32_t s2u(const void* p) {
    return (uint32_t)__cvta_generic_to_shared(p);
}
#define LDSM4(R0, R1, R2, R3, ADDR) \
    asm volatile("ldmatrix.sync.aligned.m8n8.x4.shared.b16 {%0,%1,%2,%3}, [%4];" \
                 : "=r"(R0), "=r"(R1), "=r"(R2), "=r"(R3) : "r"(ADDR))
#define CPA16(dst, src) \
    asm volatile("cp.async.cg.shared.global [%0], [%1], 16;" :: "r"(dst), "l"(src) : "memory")
#define CPC() asm volatile("cp.async.commit_group;" ::: "memory")
#define CPW1() asm volatile("cp.async.wait_group 1;" ::: "memory")
#define CPW0() asm volatile("cp.async.wait_group 0;" ::: "memory")

// ---------------------------------------------------------------------------
// Prep kernels
// ---------------------------------------------------------------------------
__global__ void split_x_kernel(const float* __restrict__ x) {
    size_t u = (size_t)blockIdx.x * 256 + threadIdx.x;
    float2 v = *(const float2*)&x[2 * u];
    g_xh[u] = hpack(v.x, v.y);
}

__global__ void split_wqkv_kernel(const float* __restrict__ Wq,
                                  const float* __restrict__ Wk,
                                  const float* __restrict__ Wv) {
    size_t u = (size_t)blockIdx.x * 256 + threadIdx.x;
    int n = u & 63;
    size_t t = u >> 6;
    int kp = (int)(t % 384);
    int mh = (int)(t / 384);
    const float* W = (mh < 12) ? Wq : (mh < 24) ? Wk : Wv;
    const float* base = W + (size_t)(mh % 12) * D_ * DH_;
    float a = base[(size_t)(2 * kp) * 64 + n];
    float b = base[(size_t)(2 * kp + 1) * 64 + n];
    uint32_t h, l; hsplit2(a, b, h, l);
    size_t o = ((size_t)mh * 64 + n) * 384 + kp;
    g_wqkv[o] = h; g_wqkv[WQKVTOT + o] = l;
}

__global__ void split_wo_kernel(const float* __restrict__ Wo) {
    size_t u = (size_t)blockIdx.x * 256 + threadIdx.x;
    int n = (int)(u % 768);
    int kp = (int)(u / 768);
    float a = Wo[(size_t)(2 * kp) * 768 + n];
    float b = Wo[(size_t)(2 * kp + 1) * 768 + n];
    uint32_t h, l; hsplit2(a, b, h, l);
    size_t o = (size_t)n * 384 + kp;
    g_wo[o] = h; g_wo[WOTOT + o] = l;
}

// ---------------------------------------------------------------------------
// Kernel 1: fused QKV projection, fp16x2 + ldmatrix, 3-stage cp.async.
// grid = (64, 36), block = 256 (8 warps 4x2), CTA tile 128x64, k-chunk 32.
// ---------------------------------------------------------------------------
__global__ __launch_bounds__(256) void qkv_gemm(
    const float* __restrict__ bq, const float* __restrict__ bk,
    const float* __restrict__ bv)
{
    extern __shared__ __align__(16) uint32_t smq[];

    const int tid = threadIdx.x, lane = tid & 31, w = tid >> 5;
    const int wy = w >> 1, wx = w & 1;
    const int lr = lane & 7, lm = lane >> 3;
    const int row0 = blockIdx.x * 128;
    const int mh = blockIdx.y, m = mh / 12, h = mh % 12;
    const float* bias = (m == 0) ? bq : (m == 1) ? bk : bv;
    const float* bh = bias + h * 64;
    const uint32_t* w_h = g_wqkv + (size_t)mh * 64 * 384;
    const uint32_t* w_l = g_wqkv + WQKVTOT + (size_t)mh * 64 * 384;

    const int aoff = (wy * 32 + (lm & 1) * 8 + lr) * 20 + (lm >> 1) * 4;
    const int boff = (wx * 32 + (lm >> 1) * 8 + lr) * 20 + (lm & 1) * 4;
    const uint32_t smq_b = s2u(smq);

    auto load_chunk = [&](int ck, int st) {
        uint32_t* Ab = smq + st * 5120;
        #pragma unroll
        for (int i = 0; i < 2; i++) {
            int u = tid + i * 256;
            int r = u >> 2, q4 = u & 3;
            CPA16(s2u(&Ab[r * 20 + 4 * q4]),
                  &g_xh[(size_t)(row0 + r) * 384 + ck * 16 + 4 * q4]);
        }
        uint32_t* Bb = Ab + 2560;
        int r = tid >> 2, q4 = tid & 3;
        CPA16(s2u(&Bb[r * 20 + 4 * q4]), &w_h[(size_t)r * 384 + ck * 16 + 4 * q4]);
        CPA16(s2u(&Bb[1280 + r * 20 + 4 * q4]), &w_l[(size_t)r * 384 + ck * 16 + 4 * q4]);
    };

    float acc[2][4][4] = {};
    load_chunk(0, 0); CPC();
    load_chunk(1, 1); CPC();

    for (int ck = 0; ck < 24; ck++) {
        const int st = ck % 3;
        if (ck < 22) CPW1(); else CPW0();
        __syncthreads();
        if (ck + 2 < 24) { load_chunk(ck + 2, (ck + 2) % 3); CPC(); }

        const uint32_t abase = smq_b + (st * 5120) * 4;
        const uint32_t bbase = abase + 2560 * 4;
        #pragma unroll
        for (int kk = 0; kk < 2; kk++) {
            uint32_t a[2][4];
            #pragma unroll
            for (int mi = 0; mi < 2; mi++)
                LDSM4(a[mi][0], a[mi][1], a[mi][2], a[mi][3],
                      abase + (aoff + mi * 320 + kk * 8) * 4);
            #pragma unroll
            for (int np = 0; np < 2; np++) {
                uint32_t h0, h1, h2, h3, l0, l1, l2, l3;
                LDSM4(h0, h1, h2, h3, bbase + (boff + np * 320 + kk * 8) * 4);
                LDSM4(l0, l1, l2, l3, bbase + 5120 + (boff + np * 320 + kk * 8) * 4);
                uint32_t bh0[2] = {h0, h1}, bh1[2] = {h2, h3};
                uint32_t bl0[2] = {l0, l1}, bl1[2] = {l2, l3};
                #pragma unroll
                for (int mi = 0; mi < 2; mi++) {
                    mmah(acc[mi][2 * np],     a[mi], bh0);
                    mmah(acc[mi][2 * np],     a[mi], bl0);
                    mmah(acc[mi][2 * np + 1], a[mi], bh1);
                    mmah(acc[mi][2 * np + 1], a[mi], bl1);
                }
            }
        }
    }

    if (m == 0) {
        #pragma unroll
        for (int mi = 0; mi < 2; mi++)
            #pragma unroll
            for (int ni = 0; ni < 4; ni++) {
                int col = wx * 32 + ni * 8 + 2 * (lane & 3);
                int cp = col >> 1;
                float b0 = bh[col], b1 = bh[col + 1];
                int rl = row0 + wy * 32 + mi * 16 + (lane >> 2);
                {
                    int bb = rl >> 11, n = rl & (S_ - 1);
                    g_q[((size_t)(bb * 12 + h) * 2048 + n) * 32 + cp] =
                        hpack((acc[mi][ni][0] + b0) * QSCALE,
                              (acc[mi][ni][1] + b1) * QSCALE);
                }
                {
                    int rh2 = rl + 8;
                    int bb = rh2 >> 11, n = rh2 & (S_ - 1);
                    g_q[((size_t)(bb * 12 + h) * 2048 + n) * 32 + cp] =
                        hpack((acc[mi][ni][2] + b0) * QSCALE,
                              (acc[mi][ni][3] + b1) * QSCALE);
                }
            }
    } else if (m == 1) {
        #pragma unroll
        for (int mi = 0; mi < 2; mi++)
            #pragma unroll
            for (int ni = 0; ni < 4; ni++) {
                int col = wx * 32 + ni * 8 + 2 * (lane & 3);
                int cp = col >> 1;
                float b0 = bh[col], b1 = bh[col + 1];
                int rl = row0 + wy * 32 + mi * 16 + (lane >> 2);
                uint32_t hh, ll;
                {
                    int bb = rl >> 11, n = rl & (S_ - 1);
                    size_t o = ((size_t)(bb * 12 + h) * 2048 + n) * 32 + cp;
                    hsplit2(acc[mi][ni][0] + b0, acc[mi][ni][1] + b1, hh, ll);
                    g_k[o] = hh; g_k[QTOT + o] = ll;
                }
                {
                    int rh2 = rl + 8;
                    int bb = rh2 >> 11, n = rh2 & (S_ - 1);
                    size_t o = ((size_t)(bb * 12 + h) * 2048 + n) * 32 + cp;
                    hsplit2(acc[mi][ni][2] + b0, acc[mi][ni][3] + b1, hh, ll);
                    g_k[o] = hh; g_k[QTOT + o] = ll;
                }
            }
    } else {
        const int s1 = (lane >> 2) & 1;
        #pragma unroll
        for (int mi = 0; mi < 2; mi++)
            #pragma unroll
            for (int ni = 0; ni < 4; ni++) {
                int col = wx * 32 + ni * 8 + 2 * (lane & 3);
                float b0 = bh[col], b1 = bh[col + 1];
                float v0 = acc[mi][ni][0] + b0, v1 = acc[mi][ni][1] + b1;
                float v2 = acc[mi][ni][2] + b0, v3 = acc[mi][ni][3] + b1;
                float p0 = __shfl_xor_sync(0xffffffffu, v0, 4);
                float p1 = __shfl_xor_sync(0xffffffffu, v1, 4);
                float p2 = __shfl_xor_sync(0xffffffffu, v2, 4);
                float p3 = __shfl_xor_sync(0xffffffffu, v3, 4);
                int e = col + s1;
                float fA = s1 ? p1 : v0;
                float sA = s1 ? v1 : p0;
                float fB = s1 ? p3 : v2;
                float sB = s1 ? v3 : p2;
                int rl = row0 + wy * 32 + mi * 16 + (lane >> 2);
                int bb = rl >> 11, n = rl & (S_ - 1);
                int np = n >> 1;
                size_t base = ((size_t)(bb * 12 + h) * 64 + e) * 1024;
                uint32_t hh, ll;
                hsplit2(fA, sA, hh, ll);
                g_vt[base + np] = hh;      g_vt[VTOT + base + np] = ll;
                hsplit2(fB, sB, hh, ll);
                g_vt[base + np + 4] = hh;  g_vt[VTOT + base + np + 4] = ll;
            }
    }
}

// ---------------------------------------------------------------------------
// Kernel 2: flash attention, fp16x2 + ldmatrix, 3-stage cp.async KV tiles.
// grid = (16, 12, 4), block = 256.
// Softmax: base-2 domain; probs via ex2.approx.f16x2; row-sums (l) computed
// by an extra MMA against an all-ones B fragment (every output column of that
// tile equals the row sum, so l is register-local — no reductions).
// ---------------------------------------------------------------------------
__global__ __launch_bounds__(256) void flash_attn()
{
    extern __shared__ __align__(16) uint32_t sm2[];
    const int tid = threadIdx.x, lane = tid & 31, w = tid >> 5;
    const int lr = lane & 7, lm = lane >> 3;
    const int n0 = blockIdx.x * 128;
    const int h = blockIdx.y, b = blockIdx.z;
    const size_t qb = (size_t)(b * 12 + h) * 2048 * 32;
    const size_t vb = (size_t)(b * 12 + h) * 64 * 1024;
    const uint32_t sm_b = s2u(sm2);

    auto load_tile = [&](int t, int st) {
        uint32_t* base = sm2 + st * 9216;
        #pragma unroll
        for (int i = 0; i < 2; i++) {
            int u = tid + i * 256;
            int r = u >> 3, q4 = u & 7;
            size_t ks = qb + (size_t)(t * 64 + r) * 32 + 4 * q4;
            CPA16(s2u(&base[r * 36 + 4 * q4]),        &g_k[ks]);
            CPA16(s2u(&base[2304 + r * 36 + 4 * q4]), &g_k[QTOT + ks]);
            size_t vs = vb + (size_t)r * 1024 + t * 32 + 4 * q4;
            CPA16(s2u(&base[4608 + r * 36 + 4 * q4]), &g_vt[vs]);
            CPA16(s2u(&base[6912 + r * 36 + 4 * q4]), &g_vt[VTOT + vs]);
        }
    };

    load_tile(0, 0); CPC();
    load_tile(1, 1); CPC();

    // Stage Q (plain fp16) into stage-2 area; read fragments; reclaimed at t=0 sync.
    uint32_t* Qs = sm2 + 2 * 9216;
    #pragma unroll
    for (int i = 0; i < 4; i++) {
        int u = tid + i * 256;
        int r = u >> 3, q4 = u & 7;
        *(uint4*)&Qs[r * 36 + 4 * q4] =
            *(const uint4*)&g_q[qb + (size_t)(n0 + r) * 32 + 4 * q4];
    }
    __syncthreads();

    uint32_t qa[4][4];
    {
        const int qoff = 2 * 9216 + (w * 16 + (lm & 1) * 8 + lr) * 36 + (lm >> 1) * 4;
        #pragma unroll
        for (int kk = 0; kk < 4; kk++)
            LDSM4(qa[kk][0], qa[kk][1], qa[kk][2], qa[kk][3],
                  sm_b + (qoff + kk * 8) * 4);
    }

    const int koff = ((lm >> 1) * 8 + lr) * 36 + (lm & 1) * 4;

    float o[8][4] = {};
    float osum[4] = {};                       // l lives here (ones-column MMA)
    float m_lo = -INFINITY, m_hi = -INFINITY;

    for (int t = 0; t < 32; t++) {
        const int st = t % 3;
        if (t < 30) CPW1(); else CPW0();
        __syncthreads();
        if (t + 2 < 32) { load_tile(t + 2, (t + 2) % 3); CPC(); }

        const uint32_t khb = sm_b + (st * 9216) * 4;
        const uint32_t klb = khb + 2304 * 4;
        const uint32_t vhb = khb + 4608 * 4;
        const uint32_t vlb = khb + 6912 * 4;

        // S = Q K^T (log2-domain scores; QSCALE carries log2e)
        float s[8][4] = {};
        #pragma unroll
        for (int kk = 0; kk < 4; kk++) {
            #pragma unroll
            for (int np = 0; np < 4; np++) {
                uint32_t h0, h1, h2, h3, l0, l1, l2, l3;
                LDSM4(h0, h1, h2, h3, khb + (koff + np * 576 + kk * 8) * 4);
                LDSM4(l0, l1, l2, l3, klb + (koff + np * 576 + kk * 8) * 4);
                uint32_t bh0[2] = {h0, h1}, bh1[2] = {h2, h3};
                uint32_t bl0[2] = {l0, l1}, bl1[2] = {l2, l3};
                mmah(s[2 * np],     qa[kk], bh0);
                mmah(s[2 * np],     qa[kk], bl0);
                mmah(s[2 * np + 1], qa[kk], bh1);
                mmah(s[2 * np + 1], qa[kk], bl1);
            }
        }

        // Online softmax, base-2 (quad-local max via shfl)
        float mx_lo = -INFINITY, mx_hi = -INFINITY;
        #pragma unroll
        for (int ni = 0; ni < 8; ni++) {
            mx_lo = fmaxf(mx_lo, fmaxf(s[ni][0], s[ni][1]));
            mx_hi = fmaxf(mx_hi, fmaxf(s[ni][2], s[ni][3]));
        }
        mx_lo = fmaxf(mx_lo, __shfl_xor_sync(0xffffffffu, mx_lo, 1));
        mx_lo = fmaxf(mx_lo, __shfl_xor_sync(0xffffffffu, mx_lo, 2));
        mx_hi = fmaxf(mx_hi, __shfl_xor_sync(0xffffffffu, mx_hi, 1));
        mx_hi = fmaxf(mx_hi, __shfl_xor_sync(0xffffffffu, mx_hi, 2));

        float mn_lo = fmaxf(m_lo, mx_lo);
        float mn_hi = fmaxf(m_hi, mx_hi);
        float corr_lo = ex2(m_lo - mn_lo);
        float corr_hi = ex2(m_hi - mn_hi);
        m_lo = mn_lo;  m_hi = mn_hi;

        // Subtract max (keep scores in f32; packed to fp16 in the PV loop)
        #pragma unroll
        for (int ni = 0; ni < 8; ni++) {
            s[ni][0] -= mn_lo;  s[ni][1] -= mn_lo;
            s[ni][2] -= mn_hi;  s[ni][3] -= mn_hi;
        }

        // Rescale accumulators only when some row's max moved
        if (!__all_sync(0xffffffffu, (corr_lo == 1.0f) && (corr_hi == 1.0f))) {
            #pragma unroll
            for (int ni = 0; ni < 8; ni++) {
                o[ni][0] *= corr_lo; o[ni][1] *= corr_lo;
                o[ni][2] *= corr_hi; o[ni][3] *= corr_hi;
            }
            osum[0] *= corr_lo; osum[1] *= corr_lo;
            osum[2] *= corr_hi; osum[3] *= corr_hi;
        }

        // O += P V ; P = ex2.f16x2(packed scores); l += P·1 via ones-B MMA
        const uint32_t ones2[2] = {0x3C003C00u, 0x3C003C00u};
        #pragma unroll
        for (int j = 0; j < 4; j++) {
            uint32_t ph[4];
            ph[0] = ex2h2(hpack(s[2*j][0],   s[2*j][1]));
            ph[1] = ex2h2(hpack(s[2*j][2],   s[2*j][3]));
            ph[2] = ex2h2(hpack(s[2*j+1][0], s[2*j+1][1]));
            ph[3] = ex2h2(hpack(s[2*j+1][2], s[2*j+1][3]));
            mmah(osum, ph, ones2);
            #pragma unroll
            for (int np = 0; np < 4; np++) {
                uint32_t h0, h1, h2, h3, l0, l1, l2, l3;
                LDSM4(h0, h1, h2, h3, vhb + (koff + np * 576 + j * 8) * 4);
                LDSM4(l0, l1, l2, l3, vlb + (koff + np * 576 + j * 8) * 4);
                uint32_t bh0[2] = {h0, h1}, bh1[2] = {h2, h3};
                uint32_t bl0[2] = {l0, l1}, bl1[2] = {l2, l3};
                mmah(o[2 * np],     ph, bh0);
                mmah(o[2 * np],     ph, bl0);
                mmah(o[2 * np + 1], ph, bh1);
                mmah(o[2 * np + 1], ph, bl1);
            }
        }
    }

    // ctx: plain fp16 packed [row][384]; l is local (all ones-cols identical)
    float inv_lo = 1.0f / osum[0], inv_hi = 1.0f / osum[2];
    int rl = n0 + w * 16 + (lane >> 2);
    #pragma unroll
    for (int ni = 0; ni < 8; ni++) {
        int cp = h * 32 + ni * 4 + (lane & 3);
        g_ch[(size_t)(b * 2048 + rl) * 384 + cp] =
            hpack(o[ni][0] * inv_lo, o[ni][1] * inv_lo);
        g_ch[(size_t)(b * 2048 + rl + 8) * 384 + cp] =
            hpack(o[ni][2] * inv_hi, o[ni][3] * inv_hi);
    }
}

// ---------------------------------------------------------------------------
// Kernel 3: output projection, fp16x2 + ldmatrix, 3-stage cp.async.
// grid = (64, 12), block = 256. fp32 out + bias.
// ---------------------------------------------------------------------------
__global__ __launch_bounds__(256) void out_gemm(
    const float* __restrict__ bo, float* __restrict__ out)
{
    extern __shared__ __align__(16) uint32_t smq[];

    const int tid = threadIdx.x, lane = tid & 31, w = tid >> 5;
    const int wy = w >> 1, wx = w & 1;
    const int lr = lane & 7, lm = lane >> 3;
    const int row0 = blockIdx.x * 128;
    const int col0 = blockIdx.y * 64;
    const uint32_t* w_h = g_wo + (size_t)col0 * 384;
    const uint32_t* w_l = g_wo + WOTOT + (size_t)col0 * 384;

    const int aoff = (wy * 32 + (lm & 1) * 8 + lr) * 20 + (lm >> 1) * 4;
    const int boff = (wx * 32 + (lm >> 1) * 8 + lr) * 20 + (lm & 1) * 4;
    const uint32_t smq_b = s2u(smq);

    auto load_chunk = [&](int ck, int st) {
        uint32_t* Ab = smq + st * 5120;
        #pragma unroll
        for (int i = 0; i < 2; i++) {
            int u = tid + i * 256;
            int r = u >> 2, q4 = u & 3;
            CPA16(s2u(&Ab[r * 20 + 4 * q4]),
                  &g_ch[(size_t)(row0 + r) * 384 + ck * 16 + 4 * q4]);
        }
        uint32_t* Bb = Ab + 2560;
        int r = tid >> 2, q4 = tid & 3;
        CPA16(s2u(&Bb[r * 20 + 4 * q4]), &w_h[(size_t)r * 384 + ck * 16 + 4 * q4]);
        CPA16(s2u(&Bb[1280 + r * 20 + 4 * q4]), &w_l[(size_t)r * 384 + ck * 16 + 4 * q4]);
    };

    float acc[2][4][4] = {};
    load_chunk(0, 0); CPC();
    load_chunk(1, 1); CPC();

    for (int ck = 0; ck < 24; ck++) {
        const int st = ck % 3;
        if (ck < 22) CPW1(); else CPW0();
        __syncthreads();
        if (ck + 2 < 24) { load_chunk(ck + 2, (ck + 2) % 3); CPC(); }

        const uint32_t abase = smq_b + (st * 5120) * 4;
        const uint32_t bbase = abase + 2560 * 4;
        #pragma unroll
        for (int kk = 0; kk < 2; kk++) {
            uint32_t a[2][4];
            #pragma unroll
            for (int mi = 0; mi < 2; mi++)
                LDSM4(a[mi][0], a[mi][1], a[mi][2], a[mi][3],
                      abase + (aoff + mi * 320 + kk * 8) * 4);
            #pragma unroll
            for (int np = 0; np < 2; np++) {
                uint32_t h0, h1, h2, h3, l0, l1, l2, l3;
                LDSM4(h0, h1, h2, h3, bbase + (boff + np * 320 + kk * 8) * 4);
                LDSM4(l0, l1, l2, l3, bbase + 5120 + (boff + np * 320 + kk * 8) * 4);
                uint32_t bh0[2] = {h0, h1}, bh1[2] = {h2, h3};
                uint32_t bl0[2] = {l0, l1}, bl1[2] = {l2, l3};
                #pragma unroll
                for (int mi = 0; mi < 2; mi++) {
                    mmah(acc[mi][2 * np],     a[mi], bh0);
                    mmah(acc[mi][2 * np],     a[mi], bl0);
                    mmah(acc[mi][2 * np + 1], a[mi], bh1);
                    mmah(acc[mi][2 * np + 1], a[mi], bl1);
                }
            }
        }
    }

    #pragma unroll
    for (int mi = 0; mi < 2; mi++)
        #pragma unroll
        for (int ni = 0; ni < 4; ni++) {
            int col = col0 + wx * 32 + ni * 8 + 2 * (lane & 3);
            float b0 = bo[col], b1 = bo[col + 1];
            int rl = row0 + wy * 32 + mi * 16 + (lane >> 2);
            float2 v0, v1;
            v0.x = acc[mi][ni][0] + b0;  v0.y = acc[mi][ni][1] + b1;
            v1.x = acc[mi][ni][2] + b0;  v1.y = acc[mi][ni][3] + b1;
            *(float2*)&out[(size_t)rl * D_ + col] = v0;
            *(float2*)&out[(size_t)(rl + 8) * D_ + col] = v1;
        }
}

// ---------------------------------------------------------------------------
extern "C" void kernel_launch(void* const* d_in, const int* in_sizes, int n_in,
                              void* d_out, int out_size)
{
    const float* x  = (const float*)d_in[0];
    const float* Wq = (const float*)d_in[1];
    const float* bq = (const float*)d_in[2];
    const float* Wk = (const float*)d_in[3];
    const float* bk = (const float*)d_in[4];
    const float* Wv = (const float*)d_in[5];
    const float* bv = (const float*)d_in[6];
    const float* Wo = (const float*)d_in[7];
    const float* bo = (const float*)d_in[8];
    float* out = (float*)d_out;

    const int gemm_smem  = 3 * 5120 * (int)sizeof(uint32_t);   // 61,440 B
    const int flash_smem = 3 * 9216 * (int)sizeof(uint32_t);   // 110,592 B
    cudaFuncSetAttribute(qkv_gemm,
                         cudaFuncAttributeMaxDynamicSharedMemorySize, gemm_smem);
    cudaFuncSetAttribute(out_gemm,
                         cudaFuncAttributeMaxDynamicSharedMemorySize, gemm_smem);
    cudaFuncSetAttribute(flash_attn,
                         cudaFuncAttributeMaxDynamicSharedMemorySize, flash_smem);

    split_x_kernel<<<(int)(XTOT / 256), 256>>>(x);
    split_wqkv_kernel<<<(int)(WQKVTOT / 256), 256>>>(Wq, Wk, Wv);
    split_wo_kernel<<<(int)(WOTOT / 256), 256>>>(Wo);

    dim3 g1(64, 36);
    qkv_gemm<<<g1, 256, gemm_smem>>>(bq, bk, bv);

    dim3 g2(16, 12, 4);
    flash_attn<<<g2, 256, flash_smem>>>();

    dim3 g3(64, 12);
    out_gemm<<<g3, 256, gemm_smem>>>(bo, out);
}